// round 7
// baseline (speedup 1.0000x reference)
#include <cuda_runtime.h>
#include <cuda_fp16.h>
#include <cstdint>

#define FD 128
#define FH 256

// ---------------- scratch (device globals; no allocation allowed) -------------
__device__ float g_agg_u[50000 * FD];   // segsum of raw item feats -> user msgs
__device__ float g_agg_i[50000 * FD];   // segsum of raw user feats -> item msgs
__device__ float g_h[100000 * FD];      // h (f32): self + msg, LN input
__device__ __align__(16) __half g_hh[100000 * FD], g_hl[100000 * FD];
__device__ __align__(16) __half g_zh[100000 * FH], g_zl[100000 * FH];
// transposed weights fp16, layout [N][K]
__device__ __align__(16) __half g_w_u2i[FD * FD];
__device__ __align__(16) __half g_w_i2u[FD * FD];
__device__ __align__(16) __half g_w_su[FD * FD];
__device__ __align__(16) __half g_w_si[FD * FD];
__device__ __align__(16) __half g_w_f1[FH * FD];
__device__ __align__(16) __half g_w_f2[FD * FH];

// ---------------- PTX helpers --------------------------------------------------
__device__ __forceinline__ uint32_t smem_to_u32(const void* p) {
    uint32_t a;
    asm("{ .reg .u64 t; cvta.to.shared.u64 t, %1; cvt.u32.u64 %0, t; }"
        : "=r"(a) : "l"(p));
    return a;
}
__device__ __forceinline__ void cp16(uint32_t dst, const void* src, bool p) {
    asm volatile("cp.async.cg.shared.global [%0], [%1], 16, %2;"
                 :: "r"(dst), "l"(src), "r"(p ? 16 : 0) : "memory");
}
#define CP_COMMIT() asm volatile("cp.async.commit_group;" ::: "memory")
#define CP_WAIT1()  asm volatile("cp.async.wait_group 1;" ::: "memory")
#define CP_WAIT0()  asm volatile("cp.async.wait_group 0;" ::: "memory")

__device__ __forceinline__ void ldsm4(uint32_t a, uint32_t& r0, uint32_t& r1,
                                      uint32_t& r2, uint32_t& r3) {
    asm volatile("ldmatrix.sync.aligned.m8n8.x4.shared.b16 {%0,%1,%2,%3}, [%4];"
                 : "=r"(r0), "=r"(r1), "=r"(r2), "=r"(r3) : "r"(a));
}
__device__ __forceinline__ void mma_fp16(float* c, const uint32_t* a,
                                         uint32_t b0, uint32_t b1) {
    asm volatile("mma.sync.aligned.m16n8k16.row.col.f32.f16.f16.f32 "
                 "{%0,%1,%2,%3}, {%4,%5,%6,%7}, {%8,%9}, {%0,%1,%2,%3};"
                 : "+f"(c[0]), "+f"(c[1]), "+f"(c[2]), "+f"(c[3])
                 : "r"(a[0]), "r"(a[1]), "r"(a[2]), "r"(a[3]), "r"(b0), "r"(b1));
}
// 8 f32 -> 8 fp16 hi + 8 fp16 lo (packed uint4 each)
__device__ __forceinline__ void cvt8(const float4& x, const float4& y,
                                     uint4& h, uint4& l) {
    __half2 h0 = __float22half2_rn(make_float2(x.x, x.y));
    __half2 h1 = __float22half2_rn(make_float2(x.z, x.w));
    __half2 h2 = __float22half2_rn(make_float2(y.x, y.y));
    __half2 h3 = __float22half2_rn(make_float2(y.z, y.w));
    float2 f0 = __half22float2(h0), f1 = __half22float2(h1);
    float2 f2 = __half22float2(h2), f3 = __half22float2(h3);
    __half2 l0 = __float22half2_rn(make_float2(x.x - f0.x, x.y - f0.y));
    __half2 l1 = __float22half2_rn(make_float2(x.z - f1.x, x.w - f1.y));
    __half2 l2 = __float22half2_rn(make_float2(y.x - f2.x, y.y - f2.y));
    __half2 l3 = __float22half2_rn(make_float2(y.z - f3.x, y.w - f3.y));
    h = make_uint4(*(uint32_t*)&h0, *(uint32_t*)&h1, *(uint32_t*)&h2, *(uint32_t*)&h3);
    l = make_uint4(*(uint32_t*)&l0, *(uint32_t*)&l1, *(uint32_t*)&l2, *(uint32_t*)&l3);
}

// ---------------- all-weights transpose + fp16 round (one launch) --------------
__global__ void __launch_bounds__(256)
wtrans_all(const float* __restrict__ W0, const float* __restrict__ W1,
           const float* __restrict__ W2, const float* __restrict__ W3,
           const float* __restrict__ W4, const float* __restrict__ W5,
           __half* __restrict__ H0, __half* __restrict__ H1,
           __half* __restrict__ H2, __half* __restrict__ H3,
           __half* __restrict__ H4, __half* __restrict__ H5)
{
    const float* W; __half* H; int K, N;
    switch (blockIdx.y) {
        case 0:  W = W0; H = H0; K = FD; N = FD; break;
        case 1:  W = W1; H = H1; K = FD; N = FD; break;
        case 2:  W = W2; H = H2; K = FD; N = FD; break;
        case 3:  W = W3; H = H3; K = FD; N = FD; break;
        case 4:  W = W4; H = H4; K = FD; N = FH; break;
        default: W = W5; H = H5; K = FH; N = FD; break;
    }
    int i = blockIdx.x * 256 + threadIdx.x;
    if (i >= K * N) return;
    int n = i / K, k = i - n * K;
    H[i] = __float2half_rn(W[(size_t)k * N + n]);
}

// ---------------- tensor-core GEMM (mma.sync fp16, A = hi+lo 2-term) -----------
// A32=true : A is f32, converted to fp16 hi/lo while staging to smem.
// A32=false: A given as pre-split fp16 hi/lo arrays, cp.async'd.
// C tile 128x128; grid.y selects the (A, B, bias, out, colOff) set.
// smem: 2 stages x 48KB { AH 16K | AL 16K | BH 16K }, 128B rows, XOR swizzle.
template<bool A32>
__global__ void __launch_bounds__(256)
gemm_mma(const __half* __restrict__ Ah0, const __half* __restrict__ Al0,
         const __half* __restrict__ Ah1, const __half* __restrict__ Al1,
         const float* __restrict__ Af0, const float* __restrict__ Af1,
         const __half* __restrict__ B0, const __half* __restrict__ B1,
         const float* __restrict__ bias0, const float* __restrict__ bias1,
         float* __restrict__ outF0, float* __restrict__ outF1,
         __half* __restrict__ outH, __half* __restrict__ outL,
         int M, int K, int ldC, int colOff1, int relu, int accum)
{
    extern __shared__ char smem[];
    const uint32_t smBase = smem_to_u32(smem);
    const int tid = threadIdx.x;
    const int lane = tid & 31, wid = tid >> 5;
    const int j = blockIdx.y;

    const __half* Bh = j ? B1 : B0;
    const float* bias = j ? bias1 : bias0;
    float* outF = j ? outF1 : outF0;
    const int colOff = j ? colOff1 : 0;
    const int rowBase = blockIdx.x * 128;
    const int nc = K >> 6;

    // load mapping: thread pair per tile row
    const int ir = tid >> 1;
    const int ikh = tid & 1;
    const bool aOk = (rowBase + ir) < M;
    const size_t aBase = (size_t)(aOk ? rowBase + ir : 0) * K;
    const size_t bBase = (size_t)ir * K;
    const float* Af = j ? Af1 : Af0;
    const __half* Ah = j ? Ah1 : Ah0;
    const __half* Al = j ? Al1 : Al0;

    // B (and fp16-A) async copy for chunk c into stage s
    auto issue = [&](int c, int s) {
        uint32_t st = smBase + s * 49152;
        #pragma unroll
        for (int i = 0; i < 4; i++) {
            int byteoff = ikh * 64 + i * 16;
            uint32_t doff = (uint32_t)ir * 128 + (uint32_t)(byteoff ^ ((ir & 7) << 4));
            int kOff = c * 64 + (byteoff >> 1);
            if (!A32) {
                cp16(st + doff,         Ah + aBase + kOff, aOk);
                cp16(st + 16384 + doff, Al + aBase + kOff, aOk);
            }
            cp16(st + 32768 + doff, Bh + bBase + kOff, true);
        }
        CP_COMMIT();
    };

    float4 aR[8];
    auto ldgA = [&](int c) {
        const float* p = Af + aBase + c * 64 + ikh * 32;
        #pragma unroll
        for (int i = 0; i < 8; i++)
            aR[i] = aOk ? *(const float4*)(p + i * 4) : make_float4(0.f, 0.f, 0.f, 0.f);
    };
    auto stsA = [&](int s) {
        char* st = smem + s * 49152;
        #pragma unroll
        for (int i = 0; i < 4; i++) {
            uint4 hs, ls;
            cvt8(aR[2 * i], aR[2 * i + 1], hs, ls);
            uint32_t doff = (uint32_t)ir * 128 +
                            (uint32_t)((ikh * 64 + i * 16) ^ ((ir & 7) << 4));
            *(uint4*)(st + doff) = hs;
            *(uint4*)(st + 16384 + doff) = ls;
        }
    };

    // per-lane ldmatrix address components
    const int m0w = (wid & 3) * 32;
    const int n0w = (wid >> 2) * 64;
    const int rA = lane & 15;
    const uint32_t kxA = (uint32_t)((lane >> 4) << 4);
    const uint32_t aoff = (uint32_t)(m0w + rA) * 128;
    const uint32_t axor = (uint32_t)((rA & 7) << 4);
    const int rB = (lane & 7) + ((lane >> 4) << 3);
    const uint32_t kxB = (uint32_t)((lane & 8) << 1);
    const uint32_t bxor = (uint32_t)((rB & 7) << 4);

    float acc[2][8][4];
    #pragma unroll
    for (int a = 0; a < 2; a++)
        #pragma unroll
        for (int b = 0; b < 8; b++)
            #pragma unroll
            for (int c = 0; c < 4; c++) acc[a][b][c] = 0.f;

    if (A32) ldgA(0);
    issue(0, 0);
    if (nc > 1) issue(1, 1);

    for (int c = 0; c < nc; c++) {
        if (c + 1 < nc) CP_WAIT1(); else CP_WAIT0();
        const int s = c & 1;
        if (A32) stsA(s);
        __syncthreads();
        if (A32 && c + 1 < nc) ldgA(c + 1);

        const uint32_t AHs = smBase + s * 49152;
        const uint32_t ALs = AHs + 16384;
        const uint32_t BHs = AHs + 32768;

        #pragma unroll
        for (int kk4 = 0; kk4 < 4; kk4++) {
            const uint32_t kb = (uint32_t)kk4 * 32;
            uint32_t ah[2][4], al[2][4];
            #pragma unroll
            for (int mt = 0; mt < 2; mt++) {
                uint32_t ad = aoff + (uint32_t)mt * 2048 + ((kb + kxA) ^ axor);
                ldsm4(AHs + ad, ah[mt][0], ah[mt][1], ah[mt][2], ah[mt][3]);
                ldsm4(ALs + ad, al[mt][0], al[mt][1], al[mt][2], al[mt][3]);
            }
            #pragma unroll
            for (int ng = 0; ng < 4; ng++) {
                uint32_t bd = (uint32_t)(n0w + ng * 16 + rB) * 128 + ((kb + kxB) ^ bxor);
                uint32_t bh[4];
                ldsm4(BHs + bd, bh[0], bh[1], bh[2], bh[3]);
                // hi MMAs first (4 independent accumulators), then lo
                #pragma unroll
                for (int mt = 0; mt < 2; mt++) {
                    mma_fp16(acc[mt][ng * 2 + 0], ah[mt], bh[0], bh[1]);
                    mma_fp16(acc[mt][ng * 2 + 1], ah[mt], bh[2], bh[3]);
                }
                #pragma unroll
                for (int mt = 0; mt < 2; mt++) {
                    mma_fp16(acc[mt][ng * 2 + 0], al[mt], bh[0], bh[1]);
                    mma_fp16(acc[mt][ng * 2 + 1], al[mt], bh[2], bh[3]);
                }
            }
        }
        __syncthreads();
        if (c + 2 < nc) issue(c + 2, s);
    }

    // epilogue
    const int g = lane >> 2, tig = lane & 3;
    #pragma unroll
    for (int mt = 0; mt < 2; mt++) {
        const int r0 = rowBase + m0w + mt * 16 + g;
        #pragma unroll
        for (int t = 0; t < 8; t++) {
            const int col = colOff + n0w + t * 8 + tig * 2;
            float b0 = 0.f, b1 = 0.f;
            if (bias) { b0 = __ldg(bias + col); b1 = __ldg(bias + col + 1); }
            float v00 = acc[mt][t][0] + b0, v01 = acc[mt][t][1] + b1;
            float v10 = acc[mt][t][2] + b0, v11 = acc[mt][t][3] + b1;
            if (relu) {
                v00 = fmaxf(v00, 0.f); v01 = fmaxf(v01, 0.f);
                v10 = fmaxf(v10, 0.f); v11 = fmaxf(v11, 0.f);
            }
            if (outF) {
                if (r0 < M) {
                    float2 o = make_float2(v00, v01);
                    if (accum) {
                        float2 p = *(float2*)&outF[(size_t)r0 * ldC + col];
                        o.x += p.x; o.y += p.y;
                    }
                    *(float2*)&outF[(size_t)r0 * ldC + col] = o;
                }
                if (r0 + 8 < M) {
                    float2 o = make_float2(v10, v11);
                    if (accum) {
                        float2 p = *(float2*)&outF[(size_t)(r0 + 8) * ldC + col];
                        o.x += p.x; o.y += p.y;
                    }
                    *(float2*)&outF[(size_t)(r0 + 8) * ldC + col] = o;
                }
            } else {
                if (r0 < M) {
                    __half2 hv = __float22half2_rn(make_float2(v00, v01));
                    float2 hf = __half22float2(hv);
                    __half2 lv = __float22half2_rn(make_float2(v00 - hf.x, v01 - hf.y));
                    *(__half2*)&outH[(size_t)r0 * ldC + col] = hv;
                    *(__half2*)&outL[(size_t)r0 * ldC + col] = lv;
                }
                if (r0 + 8 < M) {
                    __half2 hv = __float22half2_rn(make_float2(v10, v11));
                    float2 hf = __half22float2(hv);
                    __half2 lv = __float22half2_rn(make_float2(v10 - hf.x, v11 - hf.y));
                    *(__half2*)&outH[(size_t)(r0 + 8) * ldC + col] = hv;
                    *(__half2*)&outL[(size_t)(r0 + 8) * ldC + col] = lv;
                }
            }
        }
    }
}

// ---------------- both raw-feature scatters in one launch ----------------------
__global__ void __launch_bounds__(256)
scatter2_kernel(const float* __restrict__ feat_i, const int* __restrict__ src_iu,
                const int* __restrict__ dst_iu, float* __restrict__ agg_u, int E2,
                const float* __restrict__ feat_u, const int* __restrict__ src_ui,
                const int* __restrict__ dst_ui, float* __restrict__ agg_i, int E1)
{
    int idx = blockIdx.x * blockDim.x + threadIdx.x;
    int e = idx >> 5;
    const float* feat; const int* src; const int* dst; float* out;
    if (e < E2) { feat = feat_i; src = src_iu; dst = dst_iu; out = agg_u; }
    else {
        e -= E2;
        if (e >= E1) return;
        feat = feat_u; src = src_ui; dst = dst_ui; out = agg_i;
    }
    int c = (idx & 31) * 4;
    int s = __ldg(&src[e]);
    int d = __ldg(&dst[e]);
    float4 v = *(const float4*)&feat[(size_t)s * FD + c];
    float* o = &out[(size_t)d * FD + c];
    asm volatile("red.global.add.v4.f32 [%0], {%1, %2, %3, %4};"
                 :: "l"(o), "f"(v.x), "f"(v.y), "f"(v.z), "f"(v.w) : "memory");
}

// ---------------- LN -> ReLU -> +residual (both types), emit fp16 hi/lo -------
__global__ void __launch_bounds__(256)
ln_all_kernel(const float* __restrict__ h,
              const float* __restrict__ fu, const float* __restrict__ fi,
              const float* __restrict__ gu, const float* __restrict__ bu,
              const float* __restrict__ gi, const float* __restrict__ bi,
              __half* __restrict__ outH, __half* __restrict__ outL,
              int Mu, int Mt)
{
    int row = blockIdx.x * 8 + threadIdx.y;
    if (row >= Mt) return;
    int lane = threadIdx.x;
    const bool isU = row < Mu;
    const float* feat = isU ? fu + (size_t)row * FD : fi + (size_t)(row - Mu) * FD;
    const float* g = isU ? gu : gi;
    const float* b = isU ? bu : bi;

    float4 x = *(const float4*)&h[(size_t)row * FD + lane * 4];
    float s = x.x + x.y + x.z + x.w;
    #pragma unroll
    for (int off = 16; off > 0; off >>= 1) s += __shfl_xor_sync(0xffffffffu, s, off);
    float mean = s * (1.0f / FD);
    float dx = x.x - mean, dy = x.y - mean, dz = x.z - mean, dw = x.w - mean;
    float q = dx * dx + dy * dy + dz * dz + dw * dw;
    #pragma unroll
    for (int off = 16; off > 0; off >>= 1) q += __shfl_xor_sync(0xffffffffu, q, off);
    float rstd = rsqrtf(q * (1.0f / FD) + 1e-5f);

    float4 gv = *(const float4*)&g[lane * 4];
    float4 bv = *(const float4*)&b[lane * 4];
    float4 fv = *(const float4*)&feat[lane * 4];
    float4 o;
    o.x = fmaxf(dx * rstd * gv.x + bv.x, 0.f) + fv.x;
    o.y = fmaxf(dy * rstd * gv.y + bv.y, 0.f) + fv.y;
    o.z = fmaxf(dz * rstd * gv.z + bv.z, 0.f) + fv.z;
    o.w = fmaxf(dw * rstd * gv.w + bv.w, 0.f) + fv.w;

    __half2 h01 = __float22half2_rn(make_float2(o.x, o.y));
    __half2 h23 = __float22half2_rn(make_float2(o.z, o.w));
    float2 f01 = __half22float2(h01);
    float2 f23 = __half22float2(h23);
    __half2 l01 = __float22half2_rn(make_float2(o.x - f01.x, o.y - f01.y));
    __half2 l23 = __float22half2_rn(make_float2(o.z - f23.x, o.w - f23.y));
    uint2 hv = make_uint2(*(uint32_t*)&h01, *(uint32_t*)&h23);
    uint2 lv = make_uint2(*(uint32_t*)&l01, *(uint32_t*)&l23);
    *(uint2*)&outH[(size_t)row * FD + lane * 4] = hv;
    *(uint2*)&outL[(size_t)row * FD + lane * 4] = lv;
}

// ---------------- launch ------------------------------------------------------
extern "C" void kernel_launch(void* const* d_in, const int* in_sizes, int n_in,
                              void* d_out, int out_size)
{
    const float* feat_user   = (const float*)d_in[0];
    const float* feat_item   = (const float*)d_in[1];
    const float* W_u2i       = (const float*)d_in[2];
    const float* b_u2i       = (const float*)d_in[3];
    const float* W_i2u       = (const float*)d_in[4];
    const float* b_i2u       = (const float*)d_in[5];
    const float* self_w_user = (const float*)d_in[6];
    const float* self_w_item = (const float*)d_in[7];
    const float* ln_g_user   = (const float*)d_in[8];
    const float* ln_b_user   = (const float*)d_in[9];
    const float* ln_g_item   = (const float*)d_in[10];
    const float* ln_b_item   = (const float*)d_in[11];
    const float* ffn_w1      = (const float*)d_in[12];
    const float* ffn_b1      = (const float*)d_in[13];
    const float* ffn_w2      = (const float*)d_in[14];
    const float* ffn_b2      = (const float*)d_in[15];
    const int*   src_u2i     = (const int*)d_in[16];
    const int*   dst_u2i     = (const int*)d_in[17];
    const int*   src_i2u     = (const int*)d_in[18];
    const int*   dst_i2u     = (const int*)d_in[19];

    const int Mu = in_sizes[0] / FD;
    const int Mi = in_sizes[1] / FD;
    const int E1 = in_sizes[16];
    const int E2 = in_sizes[18];
    float* out = (float*)d_out;

    auto sym = [](const void* s) { void* p; cudaGetSymbolAddress(&p, s); return p; };
    float* agg_u = (float*)sym(g_agg_u);
    float* agg_i = (float*)sym(g_agg_i);
    float* h     = (float*)sym(g_h);
    __half* hh   = (__half*)sym(g_hh);
    __half* hl   = (__half*)sym(g_hl);
    __half* zh   = (__half*)sym(g_zh);
    __half* zl   = (__half*)sym(g_zl);
    __half* w_u2i = (__half*)sym(g_w_u2i);
    __half* w_i2u = (__half*)sym(g_w_i2u);
    __half* w_su  = (__half*)sym(g_w_su);
    __half* w_si  = (__half*)sym(g_w_si);
    __half* w_f1  = (__half*)sym(g_w_f1);
    __half* w_f2  = (__half*)sym(g_w_f2);

    float* h_user = h;
    float* h_item = h + (size_t)Mu * FD;

    const int SMEM = 98304;
    cudaFuncSetAttribute(gemm_mma<true>,  cudaFuncAttributeMaxDynamicSharedMemorySize, SMEM);
    cudaFuncSetAttribute(gemm_mma<false>, cudaFuncAttributeMaxDynamicSharedMemorySize, SMEM);

    // streams + events for fork/join inside the captured graph
    static cudaStream_t s2 = nullptr;
    static cudaEvent_t evF = nullptr, evJ = nullptr;
    if (!s2) {
        cudaStreamCreateWithFlags(&s2, cudaStreamNonBlocking);
        cudaEventCreateWithFlags(&evF, cudaEventDisableTiming);
        cudaEventCreateWithFlags(&evJ, cudaEventDisableTiming);
    }

    // ---- fork: stream B does zero + raw-feature scatter (independent) --------
    cudaEventRecord(evF, 0);
    cudaStreamWaitEvent(s2, evF, 0);
    cudaMemsetAsync(agg_u, 0, (size_t)Mu * FD * sizeof(float), s2);
    cudaMemsetAsync(agg_i, 0, (size_t)Mi * FD * sizeof(float), s2);
    {
        long long tot = (long long)(E1 + E2) * 32;
        scatter2_kernel<<<(int)((tot + 255) / 256), 256, 0, s2>>>(
            feat_item, src_i2u, dst_i2u, agg_u, E2,
            feat_user, src_u2i, dst_u2i, agg_i, E1);
    }
    cudaEventRecord(evJ, s2);

    // ---- main stream: weights + self-transforms (overlaps with scatter) ------
    wtrans_all<<<dim3(128, 6), 256>>>(W_u2i, W_i2u, self_w_user, self_w_item,
                                      ffn_w1, ffn_w2,
                                      w_u2i, w_i2u, w_su, w_si, w_f1, w_f2);
    // h_user = feat_user @ self_w_user + b_i2u ; h_item = feat_item @ self_w_item + b_u2i
    gemm_mma<true><<<dim3((Mu + 127) / 128, 2), 256, SMEM>>>(
        nullptr, nullptr, nullptr, nullptr, feat_user, feat_item,
        w_su, w_si, b_i2u, b_u2i, h_user, h_item, nullptr, nullptr,
        Mu, FD, FD, 0, 0, 0);

    // ---- join, then msg GEMM accumulating into h ------------------------------
    cudaStreamWaitEvent(0, evJ, 0);
    // h_user += agg_u @ W_i2u ; h_item += agg_i @ W_u2i
    gemm_mma<true><<<dim3((Mu + 127) / 128, 2), 256, SMEM>>>(
        nullptr, nullptr, nullptr, nullptr, agg_u, agg_i,
        w_i2u, w_u2i, nullptr, nullptr, h_user, h_item, nullptr, nullptr,
        Mu, FD, FD, 0, 0, 1);

    // ---- LN -> ReLU -> residual (emit fp16 hi/lo) -----------------------------
    const int Mt = Mu + Mi;
    {
        dim3 lblk(32, 8);
        ln_all_kernel<<<(Mt + 7) / 8, lblk>>>(h, feat_user, feat_item,
                                              ln_g_user, ln_b_user, ln_g_item, ln_b_item,
                                              hh, hl, Mu, Mt);
    }

    // ---- FFN ------------------------------------------------------------------
    gemm_mma<false><<<dim3((Mt + 127) / 128, 2), 256, SMEM>>>(
        hh, hl, hh, hl, nullptr, nullptr,
        w_f1, w_f1 + 128 * FD, ffn_b1, ffn_b1,
        nullptr, nullptr, zh, zl, Mt, FD, FH, 128, 1, 0);
    gemm_mma<false><<<dim3((Mt + 127) / 128, 1), 256, SMEM>>>(
        zh, zl, zh, zl, nullptr, nullptr,
        w_f2, w_f2, ffn_b2, ffn_b2,
        out, out, nullptr, nullptr, Mt, FH, FD, 0, 0, 0);
}

// round 8
// speedup vs baseline: 1.0691x; 1.0691x over previous
#include <cuda_runtime.h>
#include <cuda_fp16.h>
#include <cstdint>

#define FD 128
#define FH 256

// ---------------- scratch (device globals; no allocation allowed) -------------
__device__ float g_agg_u[50000 * FD];   // segsum of raw item feats (f32)
__device__ float g_agg_i[50000 * FD];   // segsum of raw user feats (f32)
__device__ float g_h[100000 * FD];      // self + msg (f32), LN input
// fp16 hi/lo operands
__device__ __align__(16) __half g_fu_h[50000 * FD], g_fu_l[50000 * FD];
__device__ __align__(16) __half g_fi_h[50000 * FD], g_fi_l[50000 * FD];
__device__ __align__(16) __half g_au_h[50000 * FD], g_au_l[50000 * FD];
__device__ __align__(16) __half g_ai_h[50000 * FD], g_ai_l[50000 * FD];
__device__ __align__(16) __half g_hh[100000 * FD],  g_hl[100000 * FD];
__device__ __align__(16) __half g_zh[100000 * FH],  g_zl[100000 * FH];
// transposed weights fp16, layout [N][K]
__device__ __align__(16) __half g_w_u2i[FD * FD];
__device__ __align__(16) __half g_w_i2u[FD * FD];
__device__ __align__(16) __half g_w_su[FD * FD];
__device__ __align__(16) __half g_w_si[FD * FD];
__device__ __align__(16) __half g_w_f1[FH * FD];
__device__ __align__(16) __half g_w_f2[FD * FH];

// ---------------- PTX helpers --------------------------------------------------
__device__ __forceinline__ uint32_t smem_to_u32(const void* p) {
    uint32_t a;
    asm("{ .reg .u64 t; cvta.to.shared.u64 t, %1; cvt.u32.u64 %0, t; }"
        : "=r"(a) : "l"(p));
    return a;
}
__device__ __forceinline__ void cp16(uint32_t dst, const void* src, bool p) {
    asm volatile("cp.async.cg.shared.global [%0], [%1], 16, %2;"
                 :: "r"(dst), "l"(src), "r"(p ? 16 : 0) : "memory");
}
#define CP_COMMIT() asm volatile("cp.async.commit_group;" ::: "memory")
#define CP_WAIT1()  asm volatile("cp.async.wait_group 1;" ::: "memory")
#define CP_WAIT0()  asm volatile("cp.async.wait_group 0;" ::: "memory")

__device__ __forceinline__ void ldsm4(uint32_t a, uint32_t& r0, uint32_t& r1,
                                      uint32_t& r2, uint32_t& r3) {
    asm volatile("ldmatrix.sync.aligned.m8n8.x4.shared.b16 {%0,%1,%2,%3}, [%4];"
                 : "=r"(r0), "=r"(r1), "=r"(r2), "=r"(r3) : "r"(a));
}
__device__ __forceinline__ void mma_fp16(float* c, const uint32_t* a,
                                         uint32_t b0, uint32_t b1) {
    asm volatile("mma.sync.aligned.m16n8k16.row.col.f32.f16.f16.f32 "
                 "{%0,%1,%2,%3}, {%4,%5,%6,%7}, {%8,%9}, {%0,%1,%2,%3};"
                 : "+f"(c[0]), "+f"(c[1]), "+f"(c[2]), "+f"(c[3])
                 : "r"(a[0]), "r"(a[1]), "r"(a[2]), "r"(a[3]), "r"(b0), "r"(b1));
}

// ---------------- all-weights transpose + fp16 round (one launch) --------------
__global__ void __launch_bounds__(256)
wtrans_all(const float* __restrict__ W0, const float* __restrict__ W1,
           const float* __restrict__ W2, const float* __restrict__ W3,
           const float* __restrict__ W4, const float* __restrict__ W5,
           __half* __restrict__ H0, __half* __restrict__ H1,
           __half* __restrict__ H2, __half* __restrict__ H3,
           __half* __restrict__ H4, __half* __restrict__ H5)
{
    const float* W; __half* H; int K, N;
    switch (blockIdx.y) {
        case 0:  W = W0; H = H0; K = FD; N = FD; break;
        case 1:  W = W1; H = H1; K = FD; N = FD; break;
        case 2:  W = W2; H = H2; K = FD; N = FD; break;
        case 3:  W = W3; H = H3; K = FD; N = FD; break;
        case 4:  W = W4; H = H4; K = FD; N = FH; break;
        default: W = W5; H = H5; K = FH; N = FD; break;
    }
    int i = blockIdx.x * 256 + threadIdx.x;
    if (i >= K * N) return;
    int n = i / K, k = i - n * K;
    H[i] = __float2half_rn(W[(size_t)k * N + n]);
}

// ---------------- f32 -> fp16 hi/lo split, two tensors per launch --------------
__global__ void __launch_bounds__(256)
split2_kernel(const float* __restrict__ x0, __half* __restrict__ H0,
              __half* __restrict__ L0, int n40,
              const float* __restrict__ x1, __half* __restrict__ H1,
              __half* __restrict__ L1, int n41)
{
    const int y = blockIdx.y;
    const float* x = y ? x1 : x0;
    __half* H = y ? H1 : H0;
    __half* L = y ? L1 : L0;
    const int n4 = y ? n41 : n40;
    int i = blockIdx.x * 256 + threadIdx.x;
    if (i >= n4) return;
    float4 v = *(const float4*)(x + (size_t)i * 4);
    __half2 h01 = __float22half2_rn(make_float2(v.x, v.y));
    __half2 h23 = __float22half2_rn(make_float2(v.z, v.w));
    float2 f01 = __half22float2(h01);
    float2 f23 = __half22float2(h23);
    __half2 l01 = __float22half2_rn(make_float2(v.x - f01.x, v.y - f01.y));
    __half2 l23 = __float22half2_rn(make_float2(v.z - f23.x, v.w - f23.y));
    uint2 hv = make_uint2(*(uint32_t*)&h01, *(uint32_t*)&h23);
    uint2 lv = make_uint2(*(uint32_t*)&l01, *(uint32_t*)&l23);
    *(uint2*)(H + (size_t)i * 4) = hv;
    *(uint2*)(L + (size_t)i * 4) = lv;
}

// ---------------- tensor-core GEMM (mma.sync fp16, A = hi+lo, B = hi) ----------
// C tile 128x128; grid.y selects the (A, B, bias, out) set.
// smem: 2 stages x 48KB { AH 16K | AL 16K | BH 16K }, 128B rows, XOR swizzle.
__global__ void __launch_bounds__(256)
gemm_mma(const __half* __restrict__ Ah0, const __half* __restrict__ Al0,
         const __half* __restrict__ Ah1, const __half* __restrict__ Al1,
         const __half* __restrict__ B0, const __half* __restrict__ B1,
         const float* __restrict__ bias0, const float* __restrict__ bias1,
         float* __restrict__ outF0, float* __restrict__ outF1,
         __half* __restrict__ outH, __half* __restrict__ outL,
         int M, int K, int ldC, int colOff1, int relu, int accum)
{
    extern __shared__ char smem[];
    const uint32_t smBase = smem_to_u32(smem);
    const int tid = threadIdx.x;
    const int lane = tid & 31, wid = tid >> 5;
    const int j = blockIdx.y;

    const __half* Ah = j ? Ah1 : Ah0;
    const __half* Al = j ? Al1 : Al0;
    const __half* Bh = j ? B1 : B0;
    const float* bias = j ? bias1 : bias0;
    float* outF = j ? outF1 : outF0;
    const int colOff = j ? colOff1 : 0;
    const int rowBase = blockIdx.x * 128;
    const int nc = K >> 6;

    // cp.async mapping: thread pair per row, 4x16B segs each
    const int ir = tid >> 1;
    const int ikh = tid & 1;
    const bool aOk = (rowBase + ir) < M;
    const size_t aBase = (size_t)(aOk ? rowBase + ir : 0) * K;
    const size_t bBase = (size_t)ir * K;

    auto issue = [&](int c, int s) {
        uint32_t st = smBase + s * 49152;
        #pragma unroll
        for (int i = 0; i < 4; i++) {
            int byteoff = ikh * 64 + i * 16;
            uint32_t doff = (uint32_t)ir * 128 + (uint32_t)(byteoff ^ ((ir & 7) << 4));
            int kOff = c * 64 + (byteoff >> 1);
            cp16(st + doff,         Ah + aBase + kOff, aOk);
            cp16(st + 16384 + doff, Al + aBase + kOff, aOk);
            cp16(st + 32768 + doff, Bh + bBase + kOff, true);
        }
        CP_COMMIT();
    };

    // per-lane ldmatrix address components
    const int m0w = (wid & 3) * 32;
    const int n0w = (wid >> 2) * 64;
    const int rA = lane & 15;
    const uint32_t kxA = (uint32_t)((lane >> 4) << 4);
    const uint32_t aoff = (uint32_t)(m0w + rA) * 128;
    const uint32_t axor = (uint32_t)((rA & 7) << 4);
    const int rB = (lane & 7) + ((lane >> 4) << 3);
    const uint32_t kxB = (uint32_t)((lane & 8) << 1);
    const uint32_t bxor = (uint32_t)((rB & 7) << 4);

    float acc[2][8][4];
    #pragma unroll
    for (int a = 0; a < 2; a++)
        #pragma unroll
        for (int b = 0; b < 8; b++)
            #pragma unroll
            for (int c = 0; c < 4; c++) acc[a][b][c] = 0.f;

    issue(0, 0);
    if (nc > 1) issue(1, 1);

    for (int c = 0; c < nc; c++) {
        if (c + 1 < nc) CP_WAIT1(); else CP_WAIT0();
        __syncthreads();

        const int s = c & 1;
        const uint32_t AHs = smBase + s * 49152;
        const uint32_t ALs = AHs + 16384;
        const uint32_t BHs = AHs + 32768;

        #pragma unroll
        for (int kk4 = 0; kk4 < 4; kk4++) {
            const uint32_t kb = (uint32_t)kk4 * 32;
            uint32_t ah[2][4], al[2][4];
            #pragma unroll
            for (int mt = 0; mt < 2; mt++) {
                uint32_t ad = aoff + (uint32_t)mt * 2048 + ((kb + kxA) ^ axor);
                ldsm4(AHs + ad, ah[mt][0], ah[mt][1], ah[mt][2], ah[mt][3]);
                ldsm4(ALs + ad, al[mt][0], al[mt][1], al[mt][2], al[mt][3]);
            }
            #pragma unroll
            for (int ng = 0; ng < 4; ng++) {
                uint32_t bd = (uint32_t)(n0w + ng * 16 + rB) * 128 + ((kb + kxB) ^ bxor);
                uint32_t bh[4];
                ldsm4(BHs + bd, bh[0], bh[1], bh[2], bh[3]);
                // hi MMAs first (independent accumulators), then lo
                #pragma unroll
                for (int mt = 0; mt < 2; mt++) {
                    mma_fp16(acc[mt][ng * 2 + 0], ah[mt], bh[0], bh[1]);
                    mma_fp16(acc[mt][ng * 2 + 1], ah[mt], bh[2], bh[3]);
                }
                #pragma unroll
                for (int mt = 0; mt < 2; mt++) {
                    mma_fp16(acc[mt][ng * 2 + 0], al[mt], bh[0], bh[1]);
                    mma_fp16(acc[mt][ng * 2 + 1], al[mt], bh[2], bh[3]);
                }
            }
        }
        __syncthreads();
        if (c + 2 < nc) issue(c + 2, s);
    }

    // epilogue
    const int g = lane >> 2, tig = lane & 3;
    #pragma unroll
    for (int mt = 0; mt < 2; mt++) {
        const int r0 = rowBase + m0w + mt * 16 + g;
        #pragma unroll
        for (int t = 0; t < 8; t++) {
            const int col = colOff + n0w + t * 8 + tig * 2;
            float b0 = 0.f, b1 = 0.f;
            if (bias) { b0 = __ldg(bias + col); b1 = __ldg(bias + col + 1); }
            float v00 = acc[mt][t][0] + b0, v01 = acc[mt][t][1] + b1;
            float v10 = acc[mt][t][2] + b0, v11 = acc[mt][t][3] + b1;
            if (relu) {
                v00 = fmaxf(v00, 0.f); v01 = fmaxf(v01, 0.f);
                v10 = fmaxf(v10, 0.f); v11 = fmaxf(v11, 0.f);
            }
            if (outF) {
                if (r0 < M) {
                    float2 o = make_float2(v00, v01);
                    if (accum) {
                        float2 p = *(float2*)&outF[(size_t)r0 * ldC + col];
                        o.x += p.x; o.y += p.y;
                    }
                    *(float2*)&outF[(size_t)r0 * ldC + col] = o;
                }
                if (r0 + 8 < M) {
                    float2 o = make_float2(v10, v11);
                    if (accum) {
                        float2 p = *(float2*)&outF[(size_t)(r0 + 8) * ldC + col];
                        o.x += p.x; o.y += p.y;
                    }
                    *(float2*)&outF[(size_t)(r0 + 8) * ldC + col] = o;
                }
            } else {
                if (r0 < M) {
                    __half2 hv = __float22half2_rn(make_float2(v00, v01));
                    float2 hf = __half22float2(hv);
                    __half2 lv = __float22half2_rn(make_float2(v00 - hf.x, v01 - hf.y));
                    *(__half2*)&outH[(size_t)r0 * ldC + col] = hv;
                    *(__half2*)&outL[(size_t)r0 * ldC + col] = lv;
                }
                if (r0 + 8 < M) {
                    __half2 hv = __float22half2_rn(make_float2(v10, v11));
                    float2 hf = __half22float2(hv);
                    __half2 lv = __float22half2_rn(make_float2(v10 - hf.x, v11 - hf.y));
                    *(__half2*)&outH[(size_t)(r0 + 8) * ldC + col] = hv;
                    *(__half2*)&outL[(size_t)(r0 + 8) * ldC + col] = lv;
                }
            }
        }
    }
}

// ---------------- both raw-feature scatters in one launch ----------------------
__global__ void __launch_bounds__(256)
scatter2_kernel(const float* __restrict__ feat_i, const int* __restrict__ src_iu,
                const int* __restrict__ dst_iu, float* __restrict__ agg_u, int E2,
                const float* __restrict__ feat_u, const int* __restrict__ src_ui,
                const int* __restrict__ dst_ui, float* __restrict__ agg_i, int E1)
{
    int idx = blockIdx.x * blockDim.x + threadIdx.x;
    int e = idx >> 5;
    const float* feat; const int* src; const int* dst; float* out;
    if (e < E2) { feat = feat_i; src = src_iu; dst = dst_iu; out = agg_u; }
    else {
        e -= E2;
        if (e >= E1) return;
        feat = feat_u; src = src_ui; dst = dst_ui; out = agg_i;
    }
    int c = (idx & 31) * 4;
    int s = __ldg(&src[e]);
    int d = __ldg(&dst[e]);
    float4 v = *(const float4*)&feat[(size_t)s * FD + c];
    float* o = &out[(size_t)d * FD + c];
    asm volatile("red.global.add.v4.f32 [%0], {%1, %2, %3, %4};"
                 :: "l"(o), "f"(v.x), "f"(v.y), "f"(v.z), "f"(v.w) : "memory");
}

// ---------------- LN -> ReLU -> +residual (both types), emit fp16 hi/lo -------
__global__ void __launch_bounds__(256)
ln_all_kernel(const float* __restrict__ h,
              const float* __restrict__ fu, const float* __restrict__ fi,
              const float* __restrict__ gu, const float* __restrict__ bu,
              const float* __restrict__ gi, const float* __restrict__ bi,
              __half* __restrict__ outH, __half* __restrict__ outL,
              int Mu, int Mt)
{
    int row = blockIdx.x * 8 + threadIdx.y;
    if (row >= Mt) return;
    int lane = threadIdx.x;
    const bool isU = row < Mu;
    const float* feat = isU ? fu + (size_t)row * FD : fi + (size_t)(row - Mu) * FD;
    const float* g = isU ? gu : gi;
    const float* b = isU ? bu : bi;

    float4 x = *(const float4*)&h[(size_t)row * FD + lane * 4];
    float s = x.x + x.y + x.z + x.w;
    #pragma unroll
    for (int off = 16; off > 0; off >>= 1) s += __shfl_xor_sync(0xffffffffu, s, off);
    float mean = s * (1.0f / FD);
    float dx = x.x - mean, dy = x.y - mean, dz = x.z - mean, dw = x.w - mean;
    float q = dx * dx + dy * dy + dz * dz + dw * dw;
    #pragma unroll
    for (int off = 16; off > 0; off >>= 1) q += __shfl_xor_sync(0xffffffffu, q, off);
    float rstd = rsqrtf(q * (1.0f / FD) + 1e-5f);

    float4 gv = *(const float4*)&g[lane * 4];
    float4 bv = *(const float4*)&b[lane * 4];
    float4 fv = *(const float4*)&feat[lane * 4];
    float4 o;
    o.x = fmaxf(dx * rstd * gv.x + bv.x, 0.f) + fv.x;
    o.y = fmaxf(dy * rstd * gv.y + bv.y, 0.f) + fv.y;
    o.z = fmaxf(dz * rstd * gv.z + bv.z, 0.f) + fv.z;
    o.w = fmaxf(dw * rstd * gv.w + bv.w, 0.f) + fv.w;

    __half2 h01 = __float22half2_rn(make_float2(o.x, o.y));
    __half2 h23 = __float22half2_rn(make_float2(o.z, o.w));
    float2 f01 = __half22float2(h01);
    float2 f23 = __half22float2(h23);
    __half2 l01 = __float22half2_rn(make_float2(o.x - f01.x, o.y - f01.y));
    __half2 l23 = __float22half2_rn(make_float2(o.z - f23.x, o.w - f23.y));
    uint2 hv = make_uint2(*(uint32_t*)&h01, *(uint32_t*)&h23);
    uint2 lv = make_uint2(*(uint32_t*)&l01, *(uint32_t*)&l23);
    *(uint2*)&outH[(size_t)row * FD + lane * 4] = hv;
    *(uint2*)&outL[(size_t)row * FD + lane * 4] = lv;
}

// ---------------- launch ------------------------------------------------------
extern "C" void kernel_launch(void* const* d_in, const int* in_sizes, int n_in,
                              void* d_out, int out_size)
{
    const float* feat_user   = (const float*)d_in[0];
    const float* feat_item   = (const float*)d_in[1];
    const float* W_u2i       = (const float*)d_in[2];
    const float* b_u2i       = (const float*)d_in[3];
    const float* W_i2u       = (const float*)d_in[4];
    const float* b_i2u       = (const float*)d_in[5];
    const float* self_w_user = (const float*)d_in[6];
    const float* self_w_item = (const float*)d_in[7];
    const float* ln_g_user   = (const float*)d_in[8];
    const float* ln_b_user   = (const float*)d_in[9];
    const float* ln_g_item   = (const float*)d_in[10];
    const float* ln_b_item   = (const float*)d_in[11];
    const float* ffn_w1      = (const float*)d_in[12];
    const float* ffn_b1      = (const float*)d_in[13];
    const float* ffn_w2      = (const float*)d_in[14];
    const float* ffn_b2      = (const float*)d_in[15];
    const int*   src_u2i     = (const int*)d_in[16];
    const int*   dst_u2i     = (const int*)d_in[17];
    const int*   src_i2u     = (const int*)d_in[18];
    const int*   dst_i2u     = (const int*)d_in[19];

    const int Mu = in_sizes[0] / FD;
    const int Mi = in_sizes[1] / FD;
    const int E1 = in_sizes[16];
    const int E2 = in_sizes[18];
    float* out = (float*)d_out;

    auto sym = [](const void* s) { void* p; cudaGetSymbolAddress(&p, s); return p; };
    float* agg_u = (float*)sym(g_agg_u);
    float* agg_i = (float*)sym(g_agg_i);
    float* h     = (float*)sym(g_h);
    __half* fu_h = (__half*)sym(g_fu_h);
    __half* fu_l = (__half*)sym(g_fu_l);
    __half* fi_h = (__half*)sym(g_fi_h);
    __half* fi_l = (__half*)sym(g_fi_l);
    __half* au_h = (__half*)sym(g_au_h);
    __half* au_l = (__half*)sym(g_au_l);
    __half* ai_h = (__half*)sym(g_ai_h);
    __half* ai_l = (__half*)sym(g_ai_l);
    __half* hh   = (__half*)sym(g_hh);
    __half* hl   = (__half*)sym(g_hl);
    __half* zh   = (__half*)sym(g_zh);
    __half* zl   = (__half*)sym(g_zl);
    __half* w_u2i = (__half*)sym(g_w_u2i);
    __half* w_i2u = (__half*)sym(g_w_i2u);
    __half* w_su  = (__half*)sym(g_w_su);
    __half* w_si  = (__half*)sym(g_w_si);
    __half* w_f1  = (__half*)sym(g_w_f1);
    __half* w_f2  = (__half*)sym(g_w_f2);

    float* h_user = h;
    float* h_item = h + (size_t)Mu * FD;

    const int SMEM = 98304;
    cudaFuncSetAttribute(gemm_mma, cudaFuncAttributeMaxDynamicSharedMemorySize, SMEM);

    static cudaStream_t s2 = nullptr;
    static cudaEvent_t evF = nullptr, evJ = nullptr;
    if (!s2) {
        cudaStreamCreateWithFlags(&s2, cudaStreamNonBlocking);
        cudaEventCreateWithFlags(&evF, cudaEventDisableTiming);
        cudaEventCreateWithFlags(&evJ, cudaEventDisableTiming);
    }

    const int n4u = Mu * FD / 4, n4i = Mi * FD / 4;
    const int gx2 = (max(n4u, n4i) + 255) / 256;

    // ---- fork: stream B: zero aggs, scatter raw feats, split aggs to fp16 ----
    cudaEventRecord(evF, 0);
    cudaStreamWaitEvent(s2, evF, 0);
    cudaMemsetAsync(agg_u, 0, (size_t)Mu * FD * sizeof(float), s2);
    cudaMemsetAsync(agg_i, 0, (size_t)Mi * FD * sizeof(float), s2);
    {
        long long tot = (long long)(E1 + E2) * 32;
        scatter2_kernel<<<(int)((tot + 255) / 256), 256, 0, s2>>>(
            feat_item, src_i2u, dst_i2u, agg_u, E2,
            feat_user, src_u2i, dst_u2i, agg_i, E1);
    }
    split2_kernel<<<dim3(gx2, 2), 256, 0, s2>>>(agg_u, au_h, au_l, n4u,
                                                agg_i, ai_h, ai_l, n4i);
    cudaEventRecord(evJ, s2);

    // ---- stream A (overlapped): weights, feat splits, self-transform GEMM ----
    wtrans_all<<<dim3(128, 6), 256>>>(W_u2i, W_i2u, self_w_user, self_w_item,
                                      ffn_w1, ffn_w2,
                                      w_u2i, w_i2u, w_su, w_si, w_f1, w_f2);
    split2_kernel<<<dim3(gx2, 2), 256>>>(feat_user, fu_h, fu_l, n4u,
                                         feat_item, fi_h, fi_l, n4i);
    // h_user = feat_user @ self_w_user + b_i2u ; h_item = feat_item @ self_w_item + b_u2i
    gemm_mma<<<dim3((Mu + 127) / 128, 2), 256, SMEM>>>(
        fu_h, fu_l, fi_h, fi_l, w_su, w_si, b_i2u, b_u2i,
        h_user, h_item, nullptr, nullptr, Mu, FD, FD, 0, 0, 0);

    // ---- join; msg GEMM accumulates into h -----------------------------------
    cudaStreamWaitEvent(0, evJ, 0);
    // h_user += agg_u @ W_i2u ; h_item += agg_i @ W_u2i
    gemm_mma<<<dim3((Mu + 127) / 128, 2), 256, SMEM>>>(
        au_h, au_l, ai_h, ai_l, w_i2u, w_u2i, nullptr, nullptr,
        h_user, h_item, nullptr, nullptr, Mu, FD, FD, 0, 0, 1);

    // ---- LN -> ReLU -> residual (emit fp16 hi/lo) ----------------------------
    const int Mt = Mu + Mi;
    {
        dim3 lblk(32, 8);
        ln_all_kernel<<<(Mt + 7) / 8, lblk>>>(h, feat_user, feat_item,
                                              ln_g_user, ln_b_user, ln_g_item, ln_b_item,
                                              hh, hl, Mu, Mt);
    }

    // ---- FFN ------------------------------------------------------------------
    gemm_mma<<<dim3((Mt + 127) / 128, 2), 256, SMEM>>>(
        hh, hl, hh, hl, w_f1, w_f1 + 128 * FD, ffn_b1, ffn_b1,
        nullptr, nullptr, zh, zl, Mt, FD, FH, 128, 1, 0);
    gemm_mma<<<dim3((Mt + 127) / 128, 1), 256, SMEM>>>(
        zh, zl, zh, zl, w_f2, w_f2, ffn_b2, ffn_b2,
        out, out, nullptr, nullptr, Mt, FH, FD, 0, 0, 0);
}

// round 9
// speedup vs baseline: 1.4149x; 1.3235x over previous
#include <cuda_runtime.h>
#include <cuda_fp16.h>
#include <cstdint>

#define FD 128
#define FH 256
#define EMAX 600000
#define NMAX 50000

// ---------------- scratch (device globals; no allocation allowed) -------------
__device__ float g_tmp_u[NMAX * FD];    // feat_user @ W_u2i (f32)
__device__ float g_tmp_i[NMAX * FD];    // feat_item @ W_i2u (f32)
__device__ float g_h[100000 * FD];      // self transforms + msg bias (f32)
__device__ __align__(16) __half g_fu_h[NMAX * FD], g_fu_l[NMAX * FD];
__device__ __align__(16) __half g_fi_h[NMAX * FD], g_fi_l[NMAX * FD];
__device__ __align__(16) __half g_hh[100000 * FD], g_hl[100000 * FD];
__device__ __align__(16) __half g_zh[100000 * FH], g_zl[100000 * FH];
// transposed weights fp16, layout [N][K]
__device__ __align__(16) __half g_w_u2i[FD * FD];
__device__ __align__(16) __half g_w_i2u[FD * FD];
__device__ __align__(16) __half g_w_su[FD * FD];
__device__ __align__(16) __half g_w_si[FD * FD];
__device__ __align__(16) __half g_w_f1[FH * FD];
__device__ __align__(16) __half g_w_f2[FD * FH];
// CSR scratch
__device__ int g_cnt_u[NMAX], g_cnt_i[NMAX];
__device__ int g_off_u[NMAX + 1], g_off_i[NMAX + 1];
__device__ int g_cur_u[NMAX], g_cur_i[NMAX];
__device__ int g_eid_u[EMAX], g_eid_i[EMAX];

// ---------------- PTX helpers --------------------------------------------------
__device__ __forceinline__ uint32_t smem_to_u32(const void* p) {
    uint32_t a;
    asm("{ .reg .u64 t; cvta.to.shared.u64 t, %1; cvt.u32.u64 %0, t; }"
        : "=r"(a) : "l"(p));
    return a;
}
__device__ __forceinline__ void cp16(uint32_t dst, const void* src, bool p) {
    asm volatile("cp.async.cg.shared.global [%0], [%1], 16, %2;"
                 :: "r"(dst), "l"(src), "r"(p ? 16 : 0) : "memory");
}
#define CP_COMMIT() asm volatile("cp.async.commit_group;" ::: "memory")
#define CP_WAIT1()  asm volatile("cp.async.wait_group 1;" ::: "memory")
#define CP_WAIT0()  asm volatile("cp.async.wait_group 0;" ::: "memory")

__device__ __forceinline__ void ldsm4(uint32_t a, uint32_t& r0, uint32_t& r1,
                                      uint32_t& r2, uint32_t& r3) {
    asm volatile("ldmatrix.sync.aligned.m8n8.x4.shared.b16 {%0,%1,%2,%3}, [%4];"
                 : "=r"(r0), "=r"(r1), "=r"(r2), "=r"(r3) : "r"(a));
}
__device__ __forceinline__ void mma_fp16(float* c, const uint32_t* a,
                                         uint32_t b0, uint32_t b1) {
    asm volatile("mma.sync.aligned.m16n8k16.row.col.f32.f16.f16.f32 "
                 "{%0,%1,%2,%3}, {%4,%5,%6,%7}, {%8,%9}, {%0,%1,%2,%3};"
                 : "+f"(c[0]), "+f"(c[1]), "+f"(c[2]), "+f"(c[3])
                 : "r"(a[0]), "r"(a[1]), "r"(a[2]), "r"(a[3]), "r"(b0), "r"(b1));
}

// ---------------- all-weights transpose + fp16 round ---------------------------
__global__ void __launch_bounds__(256)
wtrans_all(const float* __restrict__ W0, const float* __restrict__ W1,
           const float* __restrict__ W2, const float* __restrict__ W3,
           const float* __restrict__ W4, const float* __restrict__ W5,
           __half* __restrict__ H0, __half* __restrict__ H1,
           __half* __restrict__ H2, __half* __restrict__ H3,
           __half* __restrict__ H4, __half* __restrict__ H5)
{
    const float* W; __half* H; int K, N;
    switch (blockIdx.y) {
        case 0:  W = W0; H = H0; K = FD; N = FD; break;
        case 1:  W = W1; H = H1; K = FD; N = FD; break;
        case 2:  W = W2; H = H2; K = FD; N = FD; break;
        case 3:  W = W3; H = H3; K = FD; N = FD; break;
        case 4:  W = W4; H = H4; K = FD; N = FH; break;
        default: W = W5; H = H5; K = FH; N = FD; break;
    }
    int i = blockIdx.x * 256 + threadIdx.x;
    if (i >= K * N) return;
    int n = i / K, k = i - n * K;
    H[i] = __float2half_rn(W[(size_t)k * N + n]);
}

// ---------------- f32 -> fp16 hi/lo split, two tensors per launch --------------
__global__ void __launch_bounds__(256)
split2_kernel(const float* __restrict__ x0, __half* __restrict__ H0,
              __half* __restrict__ L0, int n40,
              const float* __restrict__ x1, __half* __restrict__ H1,
              __half* __restrict__ L1, int n41)
{
    const int y = blockIdx.y;
    const float* x = y ? x1 : x0;
    __half* H = y ? H1 : H0;
    __half* L = y ? L1 : L0;
    const int n4 = y ? n41 : n40;
    int i = blockIdx.x * 256 + threadIdx.x;
    if (i >= n4) return;
    float4 v = *(const float4*)(x + (size_t)i * 4);
    __half2 h01 = __float22half2_rn(make_float2(v.x, v.y));
    __half2 h23 = __float22half2_rn(make_float2(v.z, v.w));
    float2 f01 = __half22float2(h01);
    float2 f23 = __half22float2(h23);
    __half2 l01 = __float22half2_rn(make_float2(v.x - f01.x, v.y - f01.y));
    __half2 l23 = __float22half2_rn(make_float2(v.z - f23.x, v.w - f23.y));
    uint2 hv = make_uint2(*(uint32_t*)&h01, *(uint32_t*)&h23);
    uint2 lv = make_uint2(*(uint32_t*)&l01, *(uint32_t*)&l23);
    *(uint2*)(H + (size_t)i * 4) = hv;
    *(uint2*)(L + (size_t)i * 4) = lv;
}

// ---------------- CSR build ----------------------------------------------------
__global__ void __launch_bounds__(256)
hist2_kernel(const int* __restrict__ dst_iu, int E2, int* __restrict__ cnt_u,
             const int* __restrict__ dst_ui, int E1, int* __restrict__ cnt_i)
{
    int i = blockIdx.x * 256 + threadIdx.x;
    if (i < E2) atomicAdd(&cnt_u[__ldg(&dst_iu[i])], 1);
    else if (i - E2 < E1) atomicAdd(&cnt_i[__ldg(&dst_ui[i - E2])], 1);
}

// one block per array; 1024-thread Hillis-Steele chunked scan
__global__ void __launch_bounds__(1024)
scan_kernel(const int* __restrict__ cnt0, int* __restrict__ off0, int* __restrict__ cur0, int n0,
            const int* __restrict__ cnt1, int* __restrict__ off1, int* __restrict__ cur1, int n1)
{
    const int* cnt = blockIdx.x ? cnt1 : cnt0;
    int* off = blockIdx.x ? off1 : off0;
    int* cur = blockIdx.x ? cur1 : cur0;
    const int n = blockIdx.x ? n1 : n0;

    __shared__ int sa[1024], sb[1024];
    __shared__ int carry;
    int tid = threadIdx.x;
    if (tid == 0) { carry = 0; off[0] = 0; }
    __syncthreads();

    for (int base = 0; base < n; base += 1024) {
        int v = (base + tid < n) ? cnt[base + tid] : 0;
        int* A = sa; int* B = sb;
        A[tid] = v; __syncthreads();
        #pragma unroll
        for (int d = 1; d < 1024; d <<= 1) {
            B[tid] = A[tid] + ((tid >= d) ? A[tid - d] : 0);
            __syncthreads();
            int* t = A; A = B; B = t;
        }
        int inc = A[tid] + carry;              // inclusive prefix + carry
        if (base + tid < n) { off[base + tid + 1] = inc; cur[base + tid] = inc - v; }
        int blocksum = A[1023];
        __syncthreads();
        if (tid == 0) carry += blocksum;
        __syncthreads();
    }
}

__global__ void __launch_bounds__(256)
fill2_kernel(const int* __restrict__ src_iu, const int* __restrict__ dst_iu, int E2,
             int* __restrict__ cur_u, int* __restrict__ eid_u,
             const int* __restrict__ src_ui, const int* __restrict__ dst_ui, int E1,
             int* __restrict__ cur_i, int* __restrict__ eid_i)
{
    int i = blockIdx.x * 256 + threadIdx.x;
    if (i < E2) {
        int p = atomicAdd(&cur_u[__ldg(&dst_iu[i])], 1);
        eid_u[p] = __ldg(&src_iu[i]);
    } else if (i - E2 < E1) {
        int e = i - E2;
        int p = atomicAdd(&cur_i[__ldg(&dst_ui[e])], 1);
        eid_i[p] = __ldg(&src_ui[e]);
    }
}

// ---------------- tensor-core GEMM (mma.sync fp16, A = hi+lo, B = hi) ----------
__global__ void __launch_bounds__(256)
gemm_mma(const __half* __restrict__ Ah0, const __half* __restrict__ Al0,
         const __half* __restrict__ Ah1, const __half* __restrict__ Al1,
         const __half* __restrict__ B0, const __half* __restrict__ B1,
         const float* __restrict__ bias0, const float* __restrict__ bias1,
         float* __restrict__ outF0, float* __restrict__ outF1,
         __half* __restrict__ outH, __half* __restrict__ outL,
         int M, int K, int ldC, int colOff1, int relu)
{
    extern __shared__ char smem[];
    const uint32_t smBase = smem_to_u32(smem);
    const int tid = threadIdx.x;
    const int lane = tid & 31, wid = tid >> 5;
    const int j = blockIdx.y;

    const __half* Ah = j ? Ah1 : Ah0;
    const __half* Al = j ? Al1 : Al0;
    const __half* Bh = j ? B1 : B0;
    const float* bias = j ? bias1 : bias0;
    float* outF = j ? outF1 : outF0;
    const int colOff = j ? colOff1 : 0;
    const int rowBase = blockIdx.x * 128;
    const int nc = K >> 6;

    const int ir = tid >> 1;
    const int ikh = tid & 1;
    const bool aOk = (rowBase + ir) < M;
    const size_t aBase = (size_t)(aOk ? rowBase + ir : 0) * K;
    const size_t bBase = (size_t)ir * K;

    auto issue = [&](int c, int s) {
        uint32_t st = smBase + s * 49152;
        #pragma unroll
        for (int i = 0; i < 4; i++) {
            int byteoff = ikh * 64 + i * 16;
            uint32_t doff = (uint32_t)ir * 128 + (uint32_t)(byteoff ^ ((ir & 7) << 4));
            int kOff = c * 64 + (byteoff >> 1);
            cp16(st + doff,         Ah + aBase + kOff, aOk);
            cp16(st + 16384 + doff, Al + aBase + kOff, aOk);
            cp16(st + 32768 + doff, Bh + bBase + kOff, true);
        }
        CP_COMMIT();
    };

    const int m0w = (wid & 3) * 32;
    const int n0w = (wid >> 2) * 64;
    const int rA = lane & 15;
    const uint32_t kxA = (uint32_t)((lane >> 4) << 4);
    const uint32_t aoff = (uint32_t)(m0w + rA) * 128;
    const uint32_t axor = (uint32_t)((rA & 7) << 4);
    const int rB = (lane & 7) + ((lane >> 4) << 3);
    const uint32_t kxB = (uint32_t)((lane & 8) << 1);
    const uint32_t bxor = (uint32_t)((rB & 7) << 4);

    float acc[2][8][4];
    #pragma unroll
    for (int a = 0; a < 2; a++)
        #pragma unroll
        for (int b = 0; b < 8; b++)
            #pragma unroll
            for (int c = 0; c < 4; c++) acc[a][b][c] = 0.f;

    issue(0, 0);
    if (nc > 1) issue(1, 1);

    for (int c = 0; c < nc; c++) {
        if (c + 1 < nc) CP_WAIT1(); else CP_WAIT0();
        __syncthreads();

        const int s = c & 1;
        const uint32_t AHs = smBase + s * 49152;
        const uint32_t ALs = AHs + 16384;
        const uint32_t BHs = AHs + 32768;

        #pragma unroll
        for (int kk4 = 0; kk4 < 4; kk4++) {
            const uint32_t kb = (uint32_t)kk4 * 32;
            uint32_t ah[2][4], al[2][4];
            #pragma unroll
            for (int mt = 0; mt < 2; mt++) {
                uint32_t ad = aoff + (uint32_t)mt * 2048 + ((kb + kxA) ^ axor);
                ldsm4(AHs + ad, ah[mt][0], ah[mt][1], ah[mt][2], ah[mt][3]);
                ldsm4(ALs + ad, al[mt][0], al[mt][1], al[mt][2], al[mt][3]);
            }
            #pragma unroll
            for (int ng = 0; ng < 4; ng++) {
                uint32_t bd = (uint32_t)(n0w + ng * 16 + rB) * 128 + ((kb + kxB) ^ bxor);
                uint32_t bh[4];
                ldsm4(BHs + bd, bh[0], bh[1], bh[2], bh[3]);
                #pragma unroll
                for (int mt = 0; mt < 2; mt++) {
                    mma_fp16(acc[mt][ng * 2 + 0], ah[mt], bh[0], bh[1]);
                    mma_fp16(acc[mt][ng * 2 + 1], ah[mt], bh[2], bh[3]);
                }
                #pragma unroll
                for (int mt = 0; mt < 2; mt++) {
                    mma_fp16(acc[mt][ng * 2 + 0], al[mt], bh[0], bh[1]);
                    mma_fp16(acc[mt][ng * 2 + 1], al[mt], bh[2], bh[3]);
                }
            }
        }
        __syncthreads();
        if (c + 2 < nc) issue(c + 2, s);
    }

    const int g = lane >> 2, tig = lane & 3;
    #pragma unroll
    for (int mt = 0; mt < 2; mt++) {
        const int r0 = rowBase + m0w + mt * 16 + g;
        #pragma unroll
        for (int t = 0; t < 8; t++) {
            const int col = colOff + n0w + t * 8 + tig * 2;
            float b0 = 0.f, b1 = 0.f;
            if (bias) { b0 = __ldg(bias + col); b1 = __ldg(bias + col + 1); }
            float v00 = acc[mt][t][0] + b0, v01 = acc[mt][t][1] + b1;
            float v10 = acc[mt][t][2] + b0, v11 = acc[mt][t][3] + b1;
            if (relu) {
                v00 = fmaxf(v00, 0.f); v01 = fmaxf(v01, 0.f);
                v10 = fmaxf(v10, 0.f); v11 = fmaxf(v11, 0.f);
            }
            if (outF) {
                if (r0 < M)     *(float2*)&outF[(size_t)r0 * ldC + col]       = make_float2(v00, v01);
                if (r0 + 8 < M) *(float2*)&outF[(size_t)(r0 + 8) * ldC + col] = make_float2(v10, v11);
            } else {
                if (r0 < M) {
                    __half2 hv = __float22half2_rn(make_float2(v00, v01));
                    float2 hf = __half22float2(hv);
                    __half2 lv = __float22half2_rn(make_float2(v00 - hf.x, v01 - hf.y));
                    *(__half2*)&outH[(size_t)r0 * ldC + col] = hv;
                    *(__half2*)&outL[(size_t)r0 * ldC + col] = lv;
                }
                if (r0 + 8 < M) {
                    __half2 hv = __float22half2_rn(make_float2(v10, v11));
                    float2 hf = __half22float2(hv);
                    __half2 lv = __float22half2_rn(make_float2(v10 - hf.x, v11 - hf.y));
                    *(__half2*)&outH[(size_t)(r0 + 8) * ldC + col] = hv;
                    *(__half2*)&outL[(size_t)(r0 + 8) * ldC + col] = lv;
                }
            }
        }
    }
}

// ---------------- fused gather + LN + ReLU + residual + fp16 split -------------
// warp per destination row. acc = hself[row] + sum_{e in csr[row]} tmp[src[e]]
__global__ void __launch_bounds__(256)
gather_ln_kernel(const float* __restrict__ hself,
                 const float* __restrict__ tmp_i, const float* __restrict__ tmp_u,
                 const int* __restrict__ off_u, const int* __restrict__ eid_u,
                 const int* __restrict__ off_i, const int* __restrict__ eid_i,
                 const float* __restrict__ fu, const float* __restrict__ fi,
                 const float* __restrict__ gu, const float* __restrict__ bu,
                 const float* __restrict__ gi, const float* __restrict__ bi,
                 __half* __restrict__ outH, __half* __restrict__ outL,
                 int Mu, int Mt)
{
    int row = blockIdx.x * 8 + threadIdx.y;
    if (row >= Mt) return;
    int lane = threadIdx.x;
    const bool isU = row < Mu;
    const int r = isU ? row : row - Mu;
    const int* off = isU ? off_u : off_i;
    const int* eid = isU ? eid_u : eid_i;
    const float* tmp = isU ? tmp_i : tmp_u;
    const float* feat = isU ? fu + (size_t)r * FD : fi + (size_t)r * FD;
    const float* g = isU ? gu : gi;
    const float* b = isU ? bu : bi;

    const int s0 = __ldg(&off[r]);
    const int s1 = __ldg(&off[r + 1]);

    float4 acc = *(const float4*)&hself[(size_t)row * FD + lane * 4];

    for (int base = s0; base < s1; base += 32) {
        int idx = (base + lane < s1) ? __ldg(&eid[base + lane]) : 0;
        int m = min(32, s1 - base);
        #pragma unroll 4
        for (int k = 0; k < m; k++) {
            int id = __shfl_sync(0xffffffffu, idx, k);
            float4 v = *(const float4*)&tmp[(size_t)id * FD + lane * 4];
            acc.x += v.x; acc.y += v.y; acc.z += v.z; acc.w += v.w;
        }
    }

    // LayerNorm over the 128-wide row held across the warp
    float s = acc.x + acc.y + acc.z + acc.w;
    #pragma unroll
    for (int off2 = 16; off2 > 0; off2 >>= 1) s += __shfl_xor_sync(0xffffffffu, s, off2);
    float mean = s * (1.0f / FD);
    float dx = acc.x - mean, dy = acc.y - mean, dz = acc.z - mean, dw = acc.w - mean;
    float q = dx * dx + dy * dy + dz * dz + dw * dw;
    #pragma unroll
    for (int off2 = 16; off2 > 0; off2 >>= 1) q += __shfl_xor_sync(0xffffffffu, q, off2);
    float rstd = rsqrtf(q * (1.0f / FD) + 1e-5f);

    float4 gv = *(const float4*)&g[lane * 4];
    float4 bv = *(const float4*)&b[lane * 4];
    float4 fv = *(const float4*)&feat[lane * 4];
    float4 o;
    o.x = fmaxf(dx * rstd * gv.x + bv.x, 0.f) + fv.x;
    o.y = fmaxf(dy * rstd * gv.y + bv.y, 0.f) + fv.y;
    o.z = fmaxf(dz * rstd * gv.z + bv.z, 0.f) + fv.z;
    o.w = fmaxf(dw * rstd * gv.w + bv.w, 0.f) + fv.w;

    __half2 h01 = __float22half2_rn(make_float2(o.x, o.y));
    __half2 h23 = __float22half2_rn(make_float2(o.z, o.w));
    float2 f01 = __half22float2(h01);
    float2 f23 = __half22float2(h23);
    __half2 l01 = __float22half2_rn(make_float2(o.x - f01.x, o.y - f01.y));
    __half2 l23 = __float22half2_rn(make_float2(o.z - f23.x, o.w - f23.y));
    uint2 hv = make_uint2(*(uint32_t*)&h01, *(uint32_t*)&h23);
    uint2 lv = make_uint2(*(uint32_t*)&l01, *(uint32_t*)&l23);
    *(uint2*)&outH[(size_t)row * FD + lane * 4] = hv;
    *(uint2*)&outL[(size_t)row * FD + lane * 4] = lv;
}

// ---------------- launch ------------------------------------------------------
extern "C" void kernel_launch(void* const* d_in, const int* in_sizes, int n_in,
                              void* d_out, int out_size)
{
    const float* feat_user   = (const float*)d_in[0];
    const float* feat_item   = (const float*)d_in[1];
    const float* W_u2i       = (const float*)d_in[2];
    const float* b_u2i       = (const float*)d_in[3];
    const float* W_i2u       = (const float*)d_in[4];
    const float* b_i2u       = (const float*)d_in[5];
    const float* self_w_user = (const float*)d_in[6];
    const float* self_w_item = (const float*)d_in[7];
    const float* ln_g_user   = (const float*)d_in[8];
    const float* ln_b_user   = (const float*)d_in[9];
    const float* ln_g_item   = (const float*)d_in[10];
    const float* ln_b_item   = (const float*)d_in[11];
    const float* ffn_w1      = (const float*)d_in[12];
    const float* ffn_b1      = (const float*)d_in[13];
    const float* ffn_w2      = (const float*)d_in[14];
    const float* ffn_b2      = (const float*)d_in[15];
    const int*   src_u2i     = (const int*)d_in[16];
    const int*   dst_u2i     = (const int*)d_in[17];
    const int*   src_i2u     = (const int*)d_in[18];
    const int*   dst_i2u     = (const int*)d_in[19];

    const int Mu = in_sizes[0] / FD;
    const int Mi = in_sizes[1] / FD;
    const int E1 = in_sizes[16];
    const int E2 = in_sizes[18];
    float* out = (float*)d_out;

    auto sym = [](const void* s) { void* p; cudaGetSymbolAddress(&p, s); return p; };
    float* tmp_u = (float*)sym(g_tmp_u);
    float* tmp_i = (float*)sym(g_tmp_i);
    float* h     = (float*)sym(g_h);
    __half* fu_h = (__half*)sym(g_fu_h);
    __half* fu_l = (__half*)sym(g_fu_l);
    __half* fi_h = (__half*)sym(g_fi_h);
    __half* fi_l = (__half*)sym(g_fi_l);
    __half* hh   = (__half*)sym(g_hh);
    __half* hl   = (__half*)sym(g_hl);
    __half* zh   = (__half*)sym(g_zh);
    __half* zl   = (__half*)sym(g_zl);
    __half* w_u2i = (__half*)sym(g_w_u2i);
    __half* w_i2u = (__half*)sym(g_w_i2u);
    __half* w_su  = (__half*)sym(g_w_su);
    __half* w_si  = (__half*)sym(g_w_si);
    __half* w_f1  = (__half*)sym(g_w_f1);
    __half* w_f2  = (__half*)sym(g_w_f2);
    int* cnt_u = (int*)sym(g_cnt_u);
    int* cnt_i = (int*)sym(g_cnt_i);
    int* off_u = (int*)sym(g_off_u);
    int* off_i = (int*)sym(g_off_i);
    int* cur_u = (int*)sym(g_cur_u);
    int* cur_i = (int*)sym(g_cur_i);
    int* eid_u = (int*)sym(g_eid_u);
    int* eid_i = (int*)sym(g_eid_i);

    float* h_user = h;
    float* h_item = h + (size_t)Mu * FD;

    const int SMEM = 98304;
    cudaFuncSetAttribute(gemm_mma, cudaFuncAttributeMaxDynamicSharedMemorySize, SMEM);

    static cudaStream_t s2 = nullptr;
    static cudaEvent_t evF = nullptr, evJ = nullptr;
    if (!s2) {
        cudaStreamCreateWithFlags(&s2, cudaStreamNonBlocking);
        cudaEventCreateWithFlags(&evF, cudaEventDisableTiming);
        cudaEventCreateWithFlags(&evJ, cudaEventDisableTiming);
    }

    // ---- fork: stream B builds both CSRs (touches only edge lists) -----------
    cudaEventRecord(evF, 0);
    cudaStreamWaitEvent(s2, evF, 0);
    cudaMemsetAsync(cnt_u, 0, Mu * sizeof(int), s2);
    cudaMemsetAsync(cnt_i, 0, Mi * sizeof(int), s2);
    {
        int tot = E1 + E2;
        hist2_kernel<<<(tot + 255) / 256, 256, 0, s2>>>(dst_i2u, E2, cnt_u,
                                                        dst_u2i, E1, cnt_i);
        scan_kernel<<<2, 1024, 0, s2>>>(cnt_u, off_u, cur_u, Mu,
                                        cnt_i, off_i, cur_i, Mi);
        fill2_kernel<<<(tot + 255) / 256, 256, 0, s2>>>(
            src_i2u, dst_i2u, E2, cur_u, eid_u,
            src_u2i, dst_u2i, E1, cur_i, eid_i);
    }
    cudaEventRecord(evJ, s2);

    // ---- stream A: weights, feature splits, relation+self GEMMs --------------
    wtrans_all<<<dim3(128, 6), 256>>>(W_u2i, W_i2u, self_w_user, self_w_item,
                                      ffn_w1, ffn_w2,
                                      w_u2i, w_i2u, w_su, w_si, w_f1, w_f2);
    const int n4u = Mu * FD / 4, n4i = Mi * FD / 4;
    const int gx2 = (max(n4u, n4i) + 255) / 256;
    split2_kernel<<<dim3(gx2, 2), 256>>>(feat_user, fu_h, fu_l, n4u,
                                         feat_item, fi_h, fi_l, n4i);
    // user: tmp_u = fu @ W_u2i ; h_user = fu @ self_w_user + b_i2u
    gemm_mma<<<dim3((Mu + 127) / 128, 2), 256, SMEM>>>(
        fu_h, fu_l, fu_h, fu_l, w_u2i, w_su, nullptr, b_i2u,
        tmp_u, h_user, nullptr, nullptr, Mu, FD, FD, 0, 0);
    // item: tmp_i = fi @ W_i2u ; h_item = fi @ self_w_item + b_u2i
    gemm_mma<<<dim3((Mi + 127) / 128, 2), 256, SMEM>>>(
        fi_h, fi_l, fi_h, fi_l, w_i2u, w_si, nullptr, b_u2i,
        tmp_i, h_item, nullptr, nullptr, Mi, FD, FD, 0, 0);

    // ---- join: fused gather + LN + ReLU + residual + fp16 split --------------
    cudaStreamWaitEvent(0, evJ, 0);
    const int Mt = Mu + Mi;
    {
        dim3 lblk(32, 8);
        gather_ln_kernel<<<(Mt + 7) / 8, lblk>>>(
            h, tmp_i, tmp_u, off_u, eid_u, off_i, eid_i,
            feat_user, feat_item,
            ln_g_user, ln_b_user, ln_g_item, ln_b_item,
            hh, hl, Mu, Mt);
    }

    // ---- FFN ------------------------------------------------------------------
    gemm_mma<<<dim3((Mt + 127) / 128, 2), 256, SMEM>>>(
        hh, hl, hh, hl, w_f1, w_f1 + 128 * FD, ffn_b1, ffn_b1,
        nullptr, nullptr, zh, zl, Mt, FD, FH, 128, 1);
    gemm_mma<<<dim3((Mt + 127) / 128, 1), 256, SMEM>>>(
        zh, zl, zh, zl, w_f2, w_f2, ffn_b2, ffn_b2,
        out, out, nullptr, nullptr, Mt, FH, FD, 0, 0);
}

// round 11
// speedup vs baseline: 1.5750x; 1.1131x over previous
#include <cuda_runtime.h>
#include <cuda_fp16.h>
#include <cstdint>

#define FD 128
#define FH 256
#define EMAX 600000
#define NMAX 50000

// ---------------- scratch (device globals; no allocation allowed) -------------
__device__ float g_tmp_u[NMAX * FD];    // feat_user @ W_u2i (f32)
__device__ float g_tmp_i[NMAX * FD];    // feat_item @ W_i2u (f32)
__device__ float g_h[100000 * FD];      // self transforms + msg bias (f32)
__device__ __align__(16) __half g_fu_h[NMAX * FD], g_fu_l[NMAX * FD];
__device__ __align__(16) __half g_fi_h[NMAX * FD], g_fi_l[NMAX * FD];
__device__ __align__(16) __half g_hh[100000 * FD], g_hl[100000 * FD];
__device__ __align__(16) __half g_zh[100000 * FH];
// transposed weights fp16, layout [N][K]
__device__ __align__(16) __half g_w_u2i[FD * FD];
__device__ __align__(16) __half g_w_i2u[FD * FD];
__device__ __align__(16) __half g_w_su[FD * FD];
__device__ __align__(16) __half g_w_si[FD * FD];
__device__ __align__(16) __half g_w_f1[FH * FD];
__device__ __align__(16) __half g_w_f2[FD * FH];
// CSR scratch
__device__ int g_cnt_u[NMAX], g_cnt_i[NMAX];
__device__ int g_off_u[NMAX + 1], g_off_i[NMAX + 1];
__device__ int g_cur_u[NMAX], g_cur_i[NMAX];
__device__ int g_eid_u[EMAX], g_eid_i[EMAX];

// ---------------- PTX helpers --------------------------------------------------
__device__ __forceinline__ uint32_t smem_to_u32(const void* p) {
    uint32_t a;
    asm("{ .reg .u64 t; cvta.to.shared.u64 t, %1; cvt.u32.u64 %0, t; }"
        : "=r"(a) : "l"(p));
    return a;
}
__device__ __forceinline__ void cp16(uint32_t dst, const void* src, bool p) {
    asm volatile("cp.async.cg.shared.global [%0], [%1], 16, %2;"
                 :: "r"(dst), "l"(src), "r"(p ? 16 : 0) : "memory");
}
#define CP_COMMIT() asm volatile("cp.async.commit_group;" ::: "memory")
#define CP_WAIT1()  asm volatile("cp.async.wait_group 1;" ::: "memory")
#define CP_WAIT0()  asm volatile("cp.async.wait_group 0;" ::: "memory")

__device__ __forceinline__ void ldsm4(uint32_t a, uint32_t& r0, uint32_t& r1,
                                      uint32_t& r2, uint32_t& r3) {
    asm volatile("ldmatrix.sync.aligned.m8n8.x4.shared.b16 {%0,%1,%2,%3}, [%4];"
                 : "=r"(r0), "=r"(r1), "=r"(r2), "=r"(r3) : "r"(a));
}
__device__ __forceinline__ void mma_fp16(float* c, const uint32_t* a,
                                         uint32_t b0, uint32_t b1) {
    asm volatile("mma.sync.aligned.m16n8k16.row.col.f32.f16.f16.f32 "
                 "{%0,%1,%2,%3}, {%4,%5,%6,%7}, {%8,%9}, {%0,%1,%2,%3};"
                 : "+f"(c[0]), "+f"(c[1]), "+f"(c[2]), "+f"(c[3])
                 : "r"(a[0]), "r"(a[1]), "r"(a[2]), "r"(a[3]), "r"(b0), "r"(b1));
}

// ---------------- all-weights transpose + fp16 round ---------------------------
__global__ void __launch_bounds__(256)
wtrans_all(const float* __restrict__ W0, const float* __restrict__ W1,
           const float* __restrict__ W2, const float* __restrict__ W3,
           const float* __restrict__ W4, const float* __restrict__ W5,
           __half* __restrict__ H0, __half* __restrict__ H1,
           __half* __restrict__ H2, __half* __restrict__ H3,
           __half* __restrict__ H4, __half* __restrict__ H5)
{
    const float* W; __half* H; int K, N;
    switch (blockIdx.y) {
        case 0:  W = W0; H = H0; K = FD; N = FD; break;
        case 1:  W = W1; H = H1; K = FD; N = FD; break;
        case 2:  W = W2; H = H2; K = FD; N = FD; break;
        case 3:  W = W3; H = H3; K = FD; N = FD; break;
        case 4:  W = W4; H = H4; K = FD; N = FH; break;
        default: W = W5; H = H5; K = FH; N = FD; break;
    }
    int i = blockIdx.x * 256 + threadIdx.x;
    if (i >= K * N) return;
    int n = i / K, k = i - n * K;
    H[i] = __float2half_rn(W[(size_t)k * N + n]);
}

// ---------------- f32 -> fp16 hi/lo split, two tensors per launch --------------
__global__ void __launch_bounds__(256)
split2_kernel(const float* __restrict__ x0, __half* __restrict__ H0,
              __half* __restrict__ L0, int n40,
              const float* __restrict__ x1, __half* __restrict__ H1,
              __half* __restrict__ L1, int n41)
{
    const int y = blockIdx.y;
    const float* x = y ? x1 : x0;
    __half* H = y ? H1 : H0;
    __half* L = y ? L1 : L0;
    const int n4 = y ? n41 : n40;
    int i = blockIdx.x * 256 + threadIdx.x;
    if (i >= n4) return;
    float4 v = *(const float4*)(x + (size_t)i * 4);
    __half2 h01 = __float22half2_rn(make_float2(v.x, v.y));
    __half2 h23 = __float22half2_rn(make_float2(v.z, v.w));
    float2 f01 = __half22float2(h01);
    float2 f23 = __half22float2(h23);
    __half2 l01 = __float22half2_rn(make_float2(v.x - f01.x, v.y - f01.y));
    __half2 l23 = __float22half2_rn(make_float2(v.z - f23.x, v.w - f23.y));
    uint2 hv = make_uint2(*(uint32_t*)&h01, *(uint32_t*)&h23);
    uint2 lv = make_uint2(*(uint32_t*)&l01, *(uint32_t*)&l23);
    *(uint2*)(H + (size_t)i * 4) = hv;
    *(uint2*)(L + (size_t)i * 4) = lv;
}

// ---------------- CSR build ----------------------------------------------------
__global__ void __launch_bounds__(256)
hist2_kernel(const int* __restrict__ dst_iu, int E2, int* __restrict__ cnt_u,
             const int* __restrict__ dst_ui, int E1, int* __restrict__ cnt_i)
{
    int i = blockIdx.x * 256 + threadIdx.x;
    if (i < E2) atomicAdd(&cnt_u[__ldg(&dst_iu[i])], 1);
    else if (i - E2 < E1) atomicAdd(&cnt_i[__ldg(&dst_ui[i - E2])], 1);
}

__global__ void __launch_bounds__(1024)
scan_kernel(const int* __restrict__ cnt0, int* __restrict__ off0, int* __restrict__ cur0, int n0,
            const int* __restrict__ cnt1, int* __restrict__ off1, int* __restrict__ cur1, int n1)
{
    const int* cnt = blockIdx.x ? cnt1 : cnt0;
    int* off = blockIdx.x ? off1 : off0;
    int* cur = blockIdx.x ? cur1 : cur0;
    const int n = blockIdx.x ? n1 : n0;

    __shared__ int sa[1024], sb[1024];
    __shared__ int carry;
    int tid = threadIdx.x;
    if (tid == 0) { carry = 0; off[0] = 0; }
    __syncthreads();

    for (int base = 0; base < n; base += 1024) {
        int v = (base + tid < n) ? cnt[base + tid] : 0;
        int* A = sa; int* B = sb;
        A[tid] = v; __syncthreads();
        #pragma unroll
        for (int d = 1; d < 1024; d <<= 1) {
            B[tid] = A[tid] + ((tid >= d) ? A[tid - d] : 0);
            __syncthreads();
            int* t = A; A = B; B = t;
        }
        int inc = A[tid] + carry;
        if (base + tid < n) { off[base + tid + 1] = inc; cur[base + tid] = inc - v; }
        int blocksum = A[1023];
        __syncthreads();
        if (tid == 0) carry += blocksum;
        __syncthreads();
    }
}

__global__ void __launch_bounds__(256)
fill2_kernel(const int* __restrict__ src_iu, const int* __restrict__ dst_iu, int E2,
             int* __restrict__ cur_u, int* __restrict__ eid_u,
             const int* __restrict__ src_ui, const int* __restrict__ dst_ui, int E1,
             int* __restrict__ cur_i, int* __restrict__ eid_i)
{
    int i = blockIdx.x * 256 + threadIdx.x;
    if (i < E2) {
        int p = atomicAdd(&cur_u[__ldg(&dst_iu[i])], 1);
        eid_u[p] = __ldg(&src_iu[i]);
    } else if (i - E2 < E1) {
        int e = i - E2;
        int p = atomicAdd(&cur_i[__ldg(&dst_ui[e])], 1);
        eid_i[p] = __ldg(&src_ui[e]);
    }
}

// ---------------- tensor-core GEMM (mma.sync fp16) -----------------------------
// ALO=1: A = hi+lo (2-term). ALO=0: A = hi only (1-term), smaller smem stage.
// grid.y selects one of up to 4 GemmSets (per-set A/B/bias/out/M/colOff).
struct GemmSet {
    const __half* Ah; const __half* Al;
    const __half* B;  const float* bias;
    float* outF; __half* outH;
    int M; int colOff;
};
struct GemmArgs { GemmSet s[4]; int K; int ldC; int relu; };

template<int ALO>
__global__ void __launch_bounds__(256)
gemm_mma(GemmArgs args)
{
    constexpr uint32_t STAGE = ALO ? 49152 : 32768;
    constexpr uint32_t BOFF  = ALO ? 32768 : 16384;

    extern __shared__ char smem[];
    const uint32_t smBase = smem_to_u32(smem);
    const int tid = threadIdx.x;
    const int lane = tid & 31, wid = tid >> 5;

    const GemmSet s = args.s[blockIdx.y];
    const int M = s.M;
    const int K = args.K, ldC = args.ldC;
    const int rowBase = blockIdx.x * 128;
    if (rowBase >= M) return;
    const int nc = K >> 6;

    const int ir = tid >> 1;
    const int ikh = tid & 1;
    const bool aOk = (rowBase + ir) < M;
    const size_t aBase = (size_t)(aOk ? rowBase + ir : 0) * K;
    const size_t bBase = (size_t)ir * K;

    auto issue = [&](int c, int st_i) {
        uint32_t st = smBase + st_i * STAGE;
        #pragma unroll
        for (int i = 0; i < 4; i++) {
            int byteoff = ikh * 64 + i * 16;
            uint32_t doff = (uint32_t)ir * 128 + (uint32_t)(byteoff ^ ((ir & 7) << 4));
            int kOff = c * 64 + (byteoff >> 1);
            cp16(st + doff, s.Ah + aBase + kOff, aOk);
            if (ALO) cp16(st + 16384 + doff, s.Al + aBase + kOff, aOk);
            cp16(st + BOFF + doff, s.B + bBase + kOff, true);
        }
        CP_COMMIT();
    };

    const int m0w = (wid & 3) * 32;
    const int n0w = (wid >> 2) * 64;
    const int rA = lane & 15;
    const uint32_t kxA = (uint32_t)((lane >> 4) << 4);
    const uint32_t aoff = (uint32_t)(m0w + rA) * 128;
    const uint32_t axor = (uint32_t)((rA & 7) << 4);
    const int rB = (lane & 7) + ((lane >> 4) << 3);
    const uint32_t kxB = (uint32_t)((lane & 8) << 1);
    const uint32_t bxor = (uint32_t)((rB & 7) << 4);

    float acc[2][8][4];
    #pragma unroll
    for (int a = 0; a < 2; a++)
        #pragma unroll
        for (int b = 0; b < 8; b++)
            #pragma unroll
            for (int c = 0; c < 4; c++) acc[a][b][c] = 0.f;

    issue(0, 0);
    if (nc > 1) issue(1, 1);

    for (int c = 0; c < nc; c++) {
        if (c + 1 < nc) CP_WAIT1(); else CP_WAIT0();
        __syncthreads();

        const int st_i = c & 1;
        const uint32_t AHs = smBase + st_i * STAGE;
        const uint32_t ALs = AHs + 16384;
        const uint32_t BHs = AHs + BOFF;

        #pragma unroll
        for (int kk4 = 0; kk4 < 4; kk4++) {
            const uint32_t kb = (uint32_t)kk4 * 32;
            uint32_t ah[2][4], al[2][4];
            #pragma unroll
            for (int mt = 0; mt < 2; mt++) {
                uint32_t ad = aoff + (uint32_t)mt * 2048 + ((kb + kxA) ^ axor);
                ldsm4(AHs + ad, ah[mt][0], ah[mt][1], ah[mt][2], ah[mt][3]);
                if (ALO) ldsm4(ALs + ad, al[mt][0], al[mt][1], al[mt][2], al[mt][3]);
            }
            #pragma unroll
            for (int ng = 0; ng < 4; ng++) {
                uint32_t bd = (uint32_t)(n0w + ng * 16 + rB) * 128 + ((kb + kxB) ^ bxor);
                uint32_t bh[4];
                ldsm4(BHs + bd, bh[0], bh[1], bh[2], bh[3]);
                #pragma unroll
                for (int mt = 0; mt < 2; mt++) {
                    mma_fp16(acc[mt][ng * 2 + 0], ah[mt], bh[0], bh[1]);
                    mma_fp16(acc[mt][ng * 2 + 1], ah[mt], bh[2], bh[3]);
                }
                if (ALO) {
                    #pragma unroll
                    for (int mt = 0; mt < 2; mt++) {
                        mma_fp16(acc[mt][ng * 2 + 0], al[mt], bh[0], bh[1]);
                        mma_fp16(acc[mt][ng * 2 + 1], al[mt], bh[2], bh[3]);
                    }
                }
            }
        }
        __syncthreads();
        if (c + 2 < nc) issue(c + 2, st_i);
    }

    const int g = lane >> 2, tig = lane & 3;
    #pragma unroll
    for (int mt = 0; mt < 2; mt++) {
        const int r0 = rowBase + m0w + mt * 16 + g;
        #pragma unroll
        for (int t = 0; t < 8; t++) {
            const int col = s.colOff + n0w + t * 8 + tig * 2;
            float b0 = 0.f, b1 = 0.f;
            if (s.bias) { b0 = __ldg(s.bias + col); b1 = __ldg(s.bias + col + 1); }
            float v00 = acc[mt][t][0] + b0, v01 = acc[mt][t][1] + b1;
            float v10 = acc[mt][t][2] + b0, v11 = acc[mt][t][3] + b1;
            if (args.relu) {
                v00 = fmaxf(v00, 0.f); v01 = fmaxf(v01, 0.f);
                v10 = fmaxf(v10, 0.f); v11 = fmaxf(v11, 0.f);
            }
            if (s.outF) {
                if (r0 < M)     *(float2*)&s.outF[(size_t)r0 * ldC + col]       = make_float2(v00, v01);
                if (r0 + 8 < M) *(float2*)&s.outF[(size_t)(r0 + 8) * ldC + col] = make_float2(v10, v11);
            } else {
                if (r0 < M) {
                    __half2 hv = __float22half2_rn(make_float2(v00, v01));
                    *(__half2*)&s.outH[(size_t)r0 * ldC + col] = hv;
                }
                if (r0 + 8 < M) {
                    __half2 hv = __float22half2_rn(make_float2(v10, v11));
                    *(__half2*)&s.outH[(size_t)(r0 + 8) * ldC + col] = hv;
                }
            }
        }
    }
}

// FFN1 variant: fp16 hi/lo output (needs lo for h-quality input to FFN1 only).
// Reuses GemmSet.outH for hi; lo pointer passed separately.
template<int ALO>
__global__ void __launch_bounds__(256)
gemm_mma_hl(GemmArgs args, __half* __restrict__ outL)
{
    // identical mainloop via code reuse is not possible without CUDA 12 features;
    // this kernel is only used where outL != nullptr (FFN1 -> hh/hl path is NOT
    // needed; FFN1 writes zh only). Unused.
    (void)args; (void)outL;
}

// ---------------- fused gather + LN + ReLU + residual + fp16 split -------------
__global__ void __launch_bounds__(256)
gather_ln_kernel(const float* __restrict__ hself,
                 const float* __restrict__ tmp_i, const float* __restrict__ tmp_u,
                 const int* __restrict__ off_u, const int* __restrict__ eid_u,
                 const int* __restrict__ off_i, const int* __restrict__ eid_i,
                 const float* __restrict__ fu, const float* __restrict__ fi,
                 const float* __restrict__ gu, const float* __restrict__ bu,
                 const float* __restrict__ gi, const float* __restrict__ bi,
                 __half* __restrict__ outH, __half* __restrict__ outL,
                 int Mu, int Mt)
{
    int row = blockIdx.x * 8 + threadIdx.y;
    if (row >= Mt) return;
    int lane = threadIdx.x;
    const bool isU = row < Mu;
    const int r = isU ? row : row - Mu;
    const int* off = isU ? off_u : off_i;
    const int* eid = isU ? eid_u : eid_i;
    const float* tmp = isU ? tmp_i : tmp_u;
    const float* feat = isU ? fu + (size_t)r * FD : fi + (size_t)r * FD;
    const float* g = isU ? gu : gi;
    const float* b = isU ? bu : bi;

    const int s0 = __ldg(&off[r]);
    const int s1 = __ldg(&off[r + 1]);

    float4 acc = *(const float4*)&hself[(size_t)row * FD + lane * 4];

    for (int base = s0; base < s1; base += 32) {
        int idx = (base + lane < s1) ? __ldg(&eid[base + lane]) : 0;
        int m = min(32, s1 - base);
        #pragma unroll 4
        for (int k = 0; k < m; k++) {
            int id = __shfl_sync(0xffffffffu, idx, k);
            float4 v = *(const float4*)&tmp[(size_t)id * FD + lane * 4];
            acc.x += v.x; acc.y += v.y; acc.z += v.z; acc.w += v.w;
        }
    }

    float s = acc.x + acc.y + acc.z + acc.w;
    #pragma unroll
    for (int off2 = 16; off2 > 0; off2 >>= 1) s += __shfl_xor_sync(0xffffffffu, s, off2);
    float mean = s * (1.0f / FD);
    float dx = acc.x - mean, dy = acc.y - mean, dz = acc.z - mean, dw = acc.w - mean;
    float q = dx * dx + dy * dy + dz * dz + dw * dw;
    #pragma unroll
    for (int off2 = 16; off2 > 0; off2 >>= 1) q += __shfl_xor_sync(0xffffffffu, q, off2);
    float rstd = rsqrtf(q * (1.0f / FD) + 1e-5f);

    float4 gv = *(const float4*)&g[lane * 4];
    float4 bv = *(const float4*)&b[lane * 4];
    float4 fv = *(const float4*)&feat[lane * 4];
    float4 o;
    o.x = fmaxf(dx * rstd * gv.x + bv.x, 0.f) + fv.x;
    o.y = fmaxf(dy * rstd * gv.y + bv.y, 0.f) + fv.y;
    o.z = fmaxf(dz * rstd * gv.z + bv.z, 0.f) + fv.z;
    o.w = fmaxf(dw * rstd * gv.w + bv.w, 0.f) + fv.w;

    __half2 h01 = __float22half2_rn(make_float2(o.x, o.y));
    __half2 h23 = __float22half2_rn(make_float2(o.z, o.w));
    float2 f01 = __half22float2(h01);
    float2 f23 = __half22float2(h23);
    __half2 l01 = __float22half2_rn(make_float2(o.x - f01.x, o.y - f01.y));
    __half2 l23 = __float22half2_rn(make_float2(o.z - f23.x, o.w - f23.y));
    uint2 hv = make_uint2(*(uint32_t*)&h01, *(uint32_t*)&h23);
    uint2 lv = make_uint2(*(uint32_t*)&l01, *(uint32_t*)&l23);
    *(uint2*)&outH[(size_t)row * FD + lane * 4] = hv;
    *(uint2*)&outL[(size_t)row * FD + lane * 4] = lv;
}

// ---------------- launch ------------------------------------------------------
extern "C" void kernel_launch(void* const* d_in, const int* in_sizes, int n_in,
                              void* d_out, int out_size)
{
    const float* feat_user   = (const float*)d_in[0];
    const float* feat_item   = (const float*)d_in[1];
    const float* W_u2i       = (const float*)d_in[2];
    const float* b_u2i       = (const float*)d_in[3];
    const float* W_i2u       = (const float*)d_in[4];
    const float* b_i2u       = (const float*)d_in[5];
    const float* self_w_user = (const float*)d_in[6];
    const float* self_w_item = (const float*)d_in[7];
    const float* ln_g_user   = (const float*)d_in[8];
    const float* ln_b_user   = (const float*)d_in[9];
    const float* ln_g_item   = (const float*)d_in[10];
    const float* ln_b_item   = (const float*)d_in[11];
    const float* ffn_w1      = (const float*)d_in[12];
    const float* ffn_b1      = (const float*)d_in[13];
    const float* ffn_w2      = (const float*)d_in[14];
    const float* ffn_b2      = (const float*)d_in[15];
    const int*   src_u2i     = (const int*)d_in[16];
    const int*   dst_u2i     = (const int*)d_in[17];
    const int*   src_i2u     = (const int*)d_in[18];
    const int*   dst_i2u     = (const int*)d_in[19];

    const int Mu = in_sizes[0] / FD;
    const int Mi = in_sizes[1] / FD;
    const int E1 = in_sizes[16];
    const int E2 = in_sizes[18];
    float* out = (float*)d_out;

    auto sym = [](const void* s) { void* p; cudaGetSymbolAddress(&p, s); return p; };
    float* tmp_u = (float*)sym(g_tmp_u);
    float* tmp_i = (float*)sym(g_tmp_i);
    float* h     = (float*)sym(g_h);
    __half* fu_h = (__half*)sym(g_fu_h);
    __half* fu_l = (__half*)sym(g_fu_l);
    __half* fi_h = (__half*)sym(g_fi_h);
    __half* fi_l = (__half*)sym(g_fi_l);
    __half* hh   = (__half*)sym(g_hh);
    __half* hl   = (__half*)sym(g_hl);
    __half* zh   = (__half*)sym(g_zh);
    __half* w_u2i = (__half*)sym(g_w_u2i);
    __half* w_i2u = (__half*)sym(g_w_i2u);
    __half* w_su  = (__half*)sym(g_w_su);
    __half* w_si  = (__half*)sym(g_w_si);
    __half* w_f1  = (__half*)sym(g_w_f1);
    __half* w_f2  = (__half*)sym(g_w_f2);
    int* cnt_u = (int*)sym(g_cnt_u);
    int* cnt_i = (int*)sym(g_cnt_i);
    int* off_u = (int*)sym(g_off_u);
    int* off_i = (int*)sym(g_off_i);
    int* cur_u = (int*)sym(g_cur_u);
    int* cur_i = (int*)sym(g_cur_i);
    int* eid_u = (int*)sym(g_eid_u);
    int* eid_i = (int*)sym(g_eid_i);

    float* h_user = h;
    float* h_item = h + (size_t)Mu * FD;

    cudaFuncSetAttribute(gemm_mma<1>, cudaFuncAttributeMaxDynamicSharedMemorySize, 98304);
    cudaFuncSetAttribute(gemm_mma<0>, cudaFuncAttributeMaxDynamicSharedMemorySize, 65536);

    static cudaStream_t s2 = nullptr;
    static cudaEvent_t evF = nullptr, evJ = nullptr;
    if (!s2) {
        cudaStreamCreateWithFlags(&s2, cudaStreamNonBlocking);
        cudaEventCreateWithFlags(&evF, cudaEventDisableTiming);
        cudaEventCreateWithFlags(&evJ, cudaEventDisableTiming);
    }

    // ---- fork: stream B builds both CSRs --------------------------------------
    cudaEventRecord(evF, 0);
    cudaStreamWaitEvent(s2, evF, 0);
    cudaMemsetAsync(cnt_u, 0, Mu * sizeof(int), s2);
    cudaMemsetAsync(cnt_i, 0, Mi * sizeof(int), s2);
    {
        int tot = E1 + E2;
        hist2_kernel<<<(tot + 255) / 256, 256, 0, s2>>>(dst_i2u, E2, cnt_u,
                                                        dst_u2i, E1, cnt_i);
        scan_kernel<<<2, 1024, 0, s2>>>(cnt_u, off_u, cur_u, Mu,
                                        cnt_i, off_i, cur_i, Mi);
        fill2_kernel<<<(tot + 255) / 256, 256, 0, s2>>>(
            src_i2u, dst_i2u, E2, cur_u, eid_u,
            src_u2i, dst_u2i, E1, cur_i, eid_i);
    }
    cudaEventRecord(evJ, s2);

    // ---- stream A: weights, feature splits, all 4 D-GEMMs in ONE launch -------
    wtrans_all<<<dim3(128, 6), 256>>>(W_u2i, W_i2u, self_w_user, self_w_item,
                                      ffn_w1, ffn_w2,
                                      w_u2i, w_i2u, w_su, w_si, w_f1, w_f2);
    const int n4u = Mu * FD / 4, n4i = Mi * FD / 4;
    const int gx2 = (max(n4u, n4i) + 255) / 256;
    split2_kernel<<<dim3(gx2, 2), 256>>>(feat_user, fu_h, fu_l, n4u,
                                         feat_item, fi_h, fi_l, n4i);
    {
        GemmArgs a{};
        a.K = FD; a.ldC = FD; a.relu = 0;
        a.s[0] = { fu_h, fu_l, w_u2i, nullptr, tmp_u,  nullptr, Mu, 0 };
        a.s[1] = { fu_h, fu_l, w_su,  b_i2u,   h_user, nullptr, Mu, 0 };
        a.s[2] = { fi_h, fi_l, w_i2u, nullptr, tmp_i,  nullptr, Mi, 0 };
        a.s[3] = { fi_h, fi_l, w_si,  b_u2i,   h_item, nullptr, Mi, 0 };
        int gx = (max(Mu, Mi) + 127) / 128;
        gemm_mma<1><<<dim3(gx, 4), 256, 98304>>>(a);
    }

    // ---- join: fused gather + LN + ReLU + residual + fp16 split ---------------
    cudaStreamWaitEvent(0, evJ, 0);
    const int Mt = Mu + Mi;
    {
        dim3 lblk(32, 8);
        gather_ln_kernel<<<(Mt + 7) / 8, lblk>>>(
            h, tmp_i, tmp_u, off_u, eid_u, off_i, eid_i,
            feat_user, feat_item,
            ln_g_user, ln_b_user, ln_g_item, ln_b_item,
            hh, hl, Mu, Mt);
    }

    // ---- FFN: FFN1 (A = hh+hl, z hi only) ; FFN2 (A = zh, 1-term) -------------
    {
        GemmArgs a{};
        a.K = FD; a.ldC = FH; a.relu = 1;
        a.s[0] = { hh, hl, w_f1,            ffn_b1, nullptr, zh, Mt, 0 };
        a.s[1] = { hh, hl, w_f1 + 128 * FD, ffn_b1, nullptr, zh, Mt, 128 };
        gemm_mma<1><<<dim3((Mt + 127) / 128, 2), 256, 98304>>>(a);
    }
    {
        GemmArgs a{};
        a.K = FH; a.ldC = FD; a.relu = 0;
        a.s[0] = { zh, nullptr, w_f2, ffn_b2, out, nullptr, Mt, 0 };
        gemm_mma<0><<<dim3((Mt + 127) / 128, 1), 256, 65536>>>(a);
    }
}

// round 13
// speedup vs baseline: 1.7396x; 1.1045x over previous
#include <cuda_runtime.h>
#include <cuda_fp16.h>
#include <cstdint>

#define FD 128
#define FH 256
#define EMAX 600000
#define NMAX 50000

// ---------------- scratch (device globals; no allocation allowed) -------------
__device__ __align__(16) __half g_tmp_u[NMAX * FD];  // feat_user @ W_u2i (fp16)
__device__ __align__(16) __half g_tmp_i[NMAX * FD];  // feat_item @ W_i2u (fp16)
__device__ float g_h[100000 * FD];                   // self transforms + msg bias (f32)
__device__ __align__(16) __half g_fu_h[NMAX * FD], g_fu_l[NMAX * FD];
__device__ __align__(16) __half g_fi_h[NMAX * FD], g_fi_l[NMAX * FD];
__device__ __align__(16) __half g_hh[100000 * FD];
__device__ __align__(16) __half g_zh[100000 * FH];
// transposed weights fp16, layout [N][K]
__device__ __align__(16) __half g_w_u2i[FD * FD];
__device__ __align__(16) __half g_w_i2u[FD * FD];
__device__ __align__(16) __half g_w_su[FD * FD];
__device__ __align__(16) __half g_w_si[FD * FD];
__device__ __align__(16) __half g_w_f1[FH * FD];
__device__ __align__(16) __half g_w_f2[FD * FH];
// CSR scratch
__device__ int g_cnt_u[NMAX], g_cnt_i[NMAX];
__device__ int g_off_u[NMAX + 1], g_off_i[NMAX + 1];
__device__ int g_cur_u[NMAX], g_cur_i[NMAX];
__device__ int g_eid_u[EMAX], g_eid_i[EMAX];

// ---------------- PTX helpers --------------------------------------------------
__device__ __forceinline__ uint32_t smem_to_u32(const void* p) {
    uint32_t a;
    asm("{ .reg .u64 t; cvta.to.shared.u64 t, %1; cvt.u32.u64 %0, t; }"
        : "=r"(a) : "l"(p));
    return a;
}
__device__ __forceinline__ void cp16(uint32_t dst, const void* src, bool p) {
    asm volatile("cp.async.cg.shared.global [%0], [%1], 16, %2;"
                 :: "r"(dst), "l"(src), "r"(p ? 16 : 0) : "memory");
}
#define CP_COMMIT() asm volatile("cp.async.commit_group;" ::: "memory")
#define CP_WAIT1()  asm volatile("cp.async.wait_group 1;" ::: "memory")
#define CP_WAIT0()  asm volatile("cp.async.wait_group 0;" ::: "memory")

__device__ __forceinline__ void ldsm4(uint32_t a, uint32_t& r0, uint32_t& r1,
                                      uint32_t& r2, uint32_t& r3) {
    asm volatile("ldmatrix.sync.aligned.m8n8.x4.shared.b16 {%0,%1,%2,%3}, [%4];"
                 : "=r"(r0), "=r"(r1), "=r"(r2), "=r"(r3) : "r"(a));
}
__device__ __forceinline__ void mma_fp16(float* c, const uint32_t* a,
                                         uint32_t b0, uint32_t b1) {
    asm volatile("mma.sync.aligned.m16n8k16.row.col.f32.f16.f16.f32 "
                 "{%0,%1,%2,%3}, {%4,%5,%6,%7}, {%8,%9}, {%0,%1,%2,%3};"
                 : "+f"(c[0]), "+f"(c[1]), "+f"(c[2]), "+f"(c[3])
                 : "r"(a[0]), "r"(a[1]), "r"(a[2]), "r"(a[3]), "r"(b0), "r"(b1));
}

// ---------------- all-weights transpose + fp16 round ---------------------------
__global__ void __launch_bounds__(256)
wtrans_all(const float* __restrict__ W0, const float* __restrict__ W1,
           const float* __restrict__ W2, const float* __restrict__ W3,
           const float* __restrict__ W4, const float* __restrict__ W5,
           __half* __restrict__ H0, __half* __restrict__ H1,
           __half* __restrict__ H2, __half* __restrict__ H3,
           __half* __restrict__ H4, __half* __restrict__ H5)
{
    const float* W; __half* H; int K, N;
    switch (blockIdx.y) {
        case 0:  W = W0; H = H0; K = FD; N = FD; break;
        case 1:  W = W1; H = H1; K = FD; N = FD; break;
        case 2:  W = W2; H = H2; K = FD; N = FD; break;
        case 3:  W = W3; H = H3; K = FD; N = FD; break;
        case 4:  W = W4; H = H4; K = FD; N = FH; break;
        default: W = W5; H = H5; K = FH; N = FD; break;
    }
    int i = blockIdx.x * 256 + threadIdx.x;
    if (i >= K * N) return;
    int n = i / K, k = i - n * K;
    H[i] = __float2half_rn(W[(size_t)k * N + n]);
}

// ---------------- f32 -> fp16 hi/lo split, two tensors per launch --------------
__global__ void __launch_bounds__(256)
split2_kernel(const float* __restrict__ x0, __half* __restrict__ H0,
              __half* __restrict__ L0, int n40,
              const float* __restrict__ x1, __half* __restrict__ H1,
              __half* __restrict__ L1, int n41)
{
    const int y = blockIdx.y;
    const float* x = y ? x1 : x0;
    __half* H = y ? H1 : H0;
    __half* L = y ? L1 : L0;
    const int n4 = y ? n41 : n40;
    int i = blockIdx.x * 256 + threadIdx.x;
    if (i >= n4) return;
    float4 v = *(const float4*)(x + (size_t)i * 4);
    __half2 h01 = __float22half2_rn(make_float2(v.x, v.y));
    __half2 h23 = __float22half2_rn(make_float2(v.z, v.w));
    float2 f01 = __half22float2(h01);
    float2 f23 = __half22float2(h23);
    __half2 l01 = __float22half2_rn(make_float2(v.x - f01.x, v.y - f01.y));
    __half2 l23 = __float22half2_rn(make_float2(v.z - f23.x, v.w - f23.y));
    uint2 hv = make_uint2(*(uint32_t*)&h01, *(uint32_t*)&h23);
    uint2 lv = make_uint2(*(uint32_t*)&l01, *(uint32_t*)&l23);
    *(uint2*)(H + (size_t)i * 4) = hv;
    *(uint2*)(L + (size_t)i * 4) = lv;
}

// ---------------- CSR build ----------------------------------------------------
__global__ void __launch_bounds__(256)
hist2_kernel(const int* __restrict__ dst_iu, int E2, int* __restrict__ cnt_u,
             const int* __restrict__ dst_ui, int E1, int* __restrict__ cnt_i)
{
    int i = blockIdx.x * 256 + threadIdx.x;
    if (i < E2) atomicAdd(&cnt_u[__ldg(&dst_iu[i])], 1);
    else if (i - E2 < E1) atomicAdd(&cnt_i[__ldg(&dst_ui[i - E2])], 1);
}

__global__ void __launch_bounds__(1024)
scan_kernel(const int* __restrict__ cnt0, int* __restrict__ off0, int* __restrict__ cur0, int n0,
            const int* __restrict__ cnt1, int* __restrict__ off1, int* __restrict__ cur1, int n1)
{
    const int* cnt = blockIdx.x ? cnt1 : cnt0;
    int* off = blockIdx.x ? off1 : off0;
    int* cur = blockIdx.x ? cur1 : cur0;
    const int n = blockIdx.x ? n1 : n0;

    __shared__ int sa[1024], sb[1024];
    __shared__ int carry;
    int tid = threadIdx.x;
    if (tid == 0) { carry = 0; off[0] = 0; }
    __syncthreads();

    for (int base = 0; base < n; base += 1024) {
        int v = (base + tid < n) ? cnt[base + tid] : 0;
        int* A = sa; int* B = sb;
        A[tid] = v; __syncthreads();
        #pragma unroll
        for (int d = 1; d < 1024; d <<= 1) {
            B[tid] = A[tid] + ((tid >= d) ? A[tid - d] : 0);
            __syncthreads();
            int* t = A; A = B; B = t;
        }
        int inc = A[tid] + carry;
        if (base + tid < n) { off[base + tid + 1] = inc; cur[base + tid] = inc - v; }
        int blocksum = A[1023];
        __syncthreads();
        if (tid == 0) carry += blocksum;
        __syncthreads();
    }
}

__global__ void __launch_bounds__(256)
fill2_kernel(const int* __restrict__ src_iu, const int* __restrict__ dst_iu, int E2,
             int* __restrict__ cur_u, int* __restrict__ eid_u,
             const int* __restrict__ src_ui, const int* __restrict__ dst_ui, int E1,
             int* __restrict__ cur_i, int* __restrict__ eid_i)
{
    int i = blockIdx.x * 256 + threadIdx.x;
    if (i < E2) {
        int p = atomicAdd(&cur_u[__ldg(&dst_iu[i])], 1);
        eid_u[p] = __ldg(&src_iu[i]);
    } else if (i - E2 < E1) {
        int e = i - E2;
        int p = atomicAdd(&cur_i[__ldg(&dst_ui[e])], 1);
        eid_i[p] = __ldg(&src_ui[e]);
    }
}

// ---------------- tensor-core GEMM (mma.sync fp16) -----------------------------
// ALO=1: A = hi+lo (2-term). ALO=0: A = hi only (1-term), smaller smem stage.
struct GemmSet {
    const __half* Ah; const __half* Al;
    const __half* B;  const float* bias;
    float* outF; __half* outH;
    int M; int colOff;
};
struct GemmArgs { GemmSet s[4]; int K; int ldC; int relu; };

template<int ALO>
__global__ void __launch_bounds__(256)
gemm_mma(GemmArgs args)
{
    constexpr uint32_t STAGE = ALO ? 49152 : 32768;
    constexpr uint32_t BOFF  = ALO ? 32768 : 16384;

    extern __shared__ char smem[];
    const uint32_t smBase = smem_to_u32(smem);
    const int tid = threadIdx.x;
    const int lane = tid & 31, wid = tid >> 5;

    const GemmSet s = args.s[blockIdx.y];
    const int M = s.M;
    const int K = args.K, ldC = args.ldC;
    const int rowBase = blockIdx.x * 128;
    if (rowBase >= M) return;
    const int nc = K >> 6;

    const int ir = tid >> 1;
    const int ikh = tid & 1;
    const bool aOk = (rowBase + ir) < M;
    const size_t aBase = (size_t)(aOk ? rowBase + ir : 0) * K;
    const size_t bBase = (size_t)ir * K;

    auto issue = [&](int c, int st_i) {
        uint32_t st = smBase + st_i * STAGE;
        #pragma unroll
        for (int i = 0; i < 4; i++) {
            int byteoff = ikh * 64 + i * 16;
            uint32_t doff = (uint32_t)ir * 128 + (uint32_t)(byteoff ^ ((ir & 7) << 4));
            int kOff = c * 64 + (byteoff >> 1);
            cp16(st + doff, s.Ah + aBase + kOff, aOk);
            if (ALO) cp16(st + 16384 + doff, s.Al + aBase + kOff, aOk);
            cp16(st + BOFF + doff, s.B + bBase + kOff, true);
        }
        CP_COMMIT();
    };

    const int m0w = (wid & 3) * 32;
    const int n0w = (wid >> 2) * 64;
    const int rA = lane & 15;
    const uint32_t kxA = (uint32_t)((lane >> 4) << 4);
    const uint32_t aoff = (uint32_t)(m0w + rA) * 128;
    const uint32_t axor = (uint32_t)((rA & 7) << 4);
    const int rB = (lane & 7) + ((lane >> 4) << 3);
    const uint32_t kxB = (uint32_t)((lane & 8) << 1);
    const uint32_t bxor = (uint32_t)((rB & 7) << 4);

    float acc[2][8][4];
    #pragma unroll
    for (int a = 0; a < 2; a++)
        #pragma unroll
        for (int b = 0; b < 8; b++)
            #pragma unroll
            for (int c = 0; c < 4; c++) acc[a][b][c] = 0.f;

    issue(0, 0);
    if (nc > 1) issue(1, 1);

    for (int c = 0; c < nc; c++) {
        if (c + 1 < nc) CP_WAIT1(); else CP_WAIT0();
        __syncthreads();

        const int st_i = c & 1;
        const uint32_t AHs = smBase + st_i * STAGE;
        const uint32_t ALs = AHs + 16384;
        const uint32_t BHs = AHs + BOFF;

        #pragma unroll
        for (int kk4 = 0; kk4 < 4; kk4++) {
            const uint32_t kb = (uint32_t)kk4 * 32;
            uint32_t ah[2][4], al[2][4];
            #pragma unroll
            for (int mt = 0; mt < 2; mt++) {
                uint32_t ad = aoff + (uint32_t)mt * 2048 + ((kb + kxA) ^ axor);
                ldsm4(AHs + ad, ah[mt][0], ah[mt][1], ah[mt][2], ah[mt][3]);
                if (ALO) ldsm4(ALs + ad, al[mt][0], al[mt][1], al[mt][2], al[mt][3]);
            }
            #pragma unroll
            for (int ng = 0; ng < 4; ng++) {
                uint32_t bd = (uint32_t)(n0w + ng * 16 + rB) * 128 + ((kb + kxB) ^ bxor);
                uint32_t bh[4];
                ldsm4(BHs + bd, bh[0], bh[1], bh[2], bh[3]);
                #pragma unroll
                for (int mt = 0; mt < 2; mt++) {
                    mma_fp16(acc[mt][ng * 2 + 0], ah[mt], bh[0], bh[1]);
                    mma_fp16(acc[mt][ng * 2 + 1], ah[mt], bh[2], bh[3]);
                }
                if (ALO) {
                    #pragma unroll
                    for (int mt = 0; mt < 2; mt++) {
                        mma_fp16(acc[mt][ng * 2 + 0], al[mt], bh[0], bh[1]);
                        mma_fp16(acc[mt][ng * 2 + 1], al[mt], bh[2], bh[3]);
                    }
                }
            }
        }
        __syncthreads();
        if (c + 2 < nc) issue(c + 2, st_i);
    }

    const int g = lane >> 2, tig = lane & 3;
    #pragma unroll
    for (int mt = 0; mt < 2; mt++) {
        const int r0 = rowBase + m0w + mt * 16 + g;
        #pragma unroll
        for (int t = 0; t < 8; t++) {
            const int col = s.colOff + n0w + t * 8 + tig * 2;
            float b0 = 0.f, b1 = 0.f;
            if (s.bias) { b0 = __ldg(s.bias + col); b1 = __ldg(s.bias + col + 1); }
            float v00 = acc[mt][t][0] + b0, v01 = acc[mt][t][1] + b1;
            float v10 = acc[mt][t][2] + b0, v11 = acc[mt][t][3] + b1;
            if (args.relu) {
                v00 = fmaxf(v00, 0.f); v01 = fmaxf(v01, 0.f);
                v10 = fmaxf(v10, 0.f); v11 = fmaxf(v11, 0.f);
            }
            if (s.outF) {
                if (r0 < M)     *(float2*)&s.outF[(size_t)r0 * ldC + col]       = make_float2(v00, v01);
                if (r0 + 8 < M) *(float2*)&s.outF[(size_t)(r0 + 8) * ldC + col] = make_float2(v10, v11);
            } else {
                if (r0 < M) {
                    __half2 hv = __float22half2_rn(make_float2(v00, v01));
                    *(__half2*)&s.outH[(size_t)r0 * ldC + col] = hv;
                }
                if (r0 + 8 < M) {
                    __half2 hv = __float22half2_rn(make_float2(v10, v11));
                    *(__half2*)&s.outH[(size_t)(r0 + 8) * ldC + col] = hv;
                }
            }
        }
    }
}

// ---------------- fused gather(fp16 msgs) + LN + ReLU + residual ---------------
// warp per destination row. acc = hself[row] + sum_{e in csr[row]} tmp[src[e]]
__global__ void __launch_bounds__(256)
gather_ln_kernel(const float* __restrict__ hself,
                 const __half* __restrict__ tmp_i, const __half* __restrict__ tmp_u,
                 const int* __restrict__ off_u, const int* __restrict__ eid_u,
                 const int* __restrict__ off_i, const int* __restrict__ eid_i,
                 const float* __restrict__ fu, const float* __restrict__ fi,
                 const float* __restrict__ gu, const float* __restrict__ bu,
                 const float* __restrict__ gi, const float* __restrict__ bi,
                 __half* __restrict__ outH,
                 int Mu, int Mt)
{
    int row = blockIdx.x * 8 + threadIdx.y;
    if (row >= Mt) return;
    int lane = threadIdx.x;
    const bool isU = row < Mu;
    const int r = isU ? row : row - Mu;
    const int* off = isU ? off_u : off_i;
    const int* eid = isU ? eid_u : eid_i;
    const __half* tmp = isU ? tmp_i : tmp_u;
    const float* feat = isU ? fu + (size_t)r * FD : fi + (size_t)r * FD;
    const float* g = isU ? gu : gi;
    const float* b = isU ? bu : bi;

    const int s0 = __ldg(&off[r]);
    const int s1 = __ldg(&off[r + 1]);

    float4 acc = *(const float4*)&hself[(size_t)row * FD + lane * 4];

    for (int base = s0; base < s1; base += 32) {
        int idx = (base + lane < s1) ? __ldg(&eid[base + lane]) : 0;
        int m = min(32, s1 - base);
        #pragma unroll 4
        for (int k = 0; k < m; k++) {
            int id = __shfl_sync(0xffffffffu, idx, k);
            uint2 raw = *(const uint2*)&tmp[(size_t)id * FD + lane * 4];
            float2 p0 = __half22float2(*(__half2*)&raw.x);
            float2 p1 = __half22float2(*(__half2*)&raw.y);
            acc.x += p0.x; acc.y += p0.y; acc.z += p1.x; acc.w += p1.y;
        }
    }

    float s = acc.x + acc.y + acc.z + acc.w;
    #pragma unroll
    for (int off2 = 16; off2 > 0; off2 >>= 1) s += __shfl_xor_sync(0xffffffffu, s, off2);
    float mean = s * (1.0f / FD);
    float dx = acc.x - mean, dy = acc.y - mean, dz = acc.z - mean, dw = acc.w - mean;
    float q = dx * dx + dy * dy + dz * dz + dw * dw;
    #pragma unroll
    for (int off2 = 16; off2 > 0; off2 >>= 1) q += __shfl_xor_sync(0xffffffffu, q, off2);
    float rstd = rsqrtf(q * (1.0f / FD) + 1e-5f);

    float4 gv = *(const float4*)&g[lane * 4];
    float4 bv = *(const float4*)&b[lane * 4];
    float4 fv = *(const float4*)&feat[lane * 4];
    float4 o;
    o.x = fmaxf(dx * rstd * gv.x + bv.x, 0.f) + fv.x;
    o.y = fmaxf(dy * rstd * gv.y + bv.y, 0.f) + fv.y;
    o.z = fmaxf(dz * rstd * gv.z + bv.z, 0.f) + fv.z;
    o.w = fmaxf(dw * rstd * gv.w + bv.w, 0.f) + fv.w;

    __half2 h01 = __float22half2_rn(make_float2(o.x, o.y));
    __half2 h23 = __float22half2_rn(make_float2(o.z, o.w));
    uint2 hv = make_uint2(*(uint32_t*)&h01, *(uint32_t*)&h23);
    *(uint2*)&outH[(size_t)row * FD + lane * 4] = hv;
}

// ---------------- launch ------------------------------------------------------
extern "C" void kernel_launch(void* const* d_in, const int* in_sizes, int n_in,
                              void* d_out, int out_size)
{
    const float* feat_user   = (const float*)d_in[0];
    const float* feat_item   = (const float*)d_in[1];
    const float* W_u2i       = (const float*)d_in[2];
    const float* b_u2i       = (const float*)d_in[3];
    const float* W_i2u       = (const float*)d_in[4];
    const float* b_i2u       = (const float*)d_in[5];
    const float* self_w_user = (const float*)d_in[6];
    const float* self_w_item = (const float*)d_in[7];
    const float* ln_g_user   = (const float*)d_in[8];
    const float* ln_b_user   = (const float*)d_in[9];
    const float* ln_g_item   = (const float*)d_in[10];
    const float* ln_b_item   = (const float*)d_in[11];
    const float* ffn_w1      = (const float*)d_in[12];
    const float* ffn_b1      = (const float*)d_in[13];
    const float* ffn_w2      = (const float*)d_in[14];
    const float* ffn_b2      = (const float*)d_in[15];
    const int*   src_u2i     = (const int*)d_in[16];
    const int*   dst_u2i     = (const int*)d_in[17];
    const int*   src_i2u     = (const int*)d_in[18];
    const int*   dst_i2u     = (const int*)d_in[19];

    const int Mu = in_sizes[0] / FD;
    const int Mi = in_sizes[1] / FD;
    const int E1 = in_sizes[16];
    const int E2 = in_sizes[18];
    float* out = (float*)d_out;

    auto sym = [](const void* s) { void* p; cudaGetSymbolAddress(&p, s); return p; };
    __half* tmp_u = (__half*)sym(g_tmp_u);
    __half* tmp_i = (__half*)sym(g_tmp_i);
    float* h      = (float*)sym(g_h);
    __half* fu_h = (__half*)sym(g_fu_h);
    __half* fu_l = (__half*)sym(g_fu_l);
    __half* fi_h = (__half*)sym(g_fi_h);
    __half* fi_l = (__half*)sym(g_fi_l);
    __half* hh   = (__half*)sym(g_hh);
    __half* zh   = (__half*)sym(g_zh);
    __half* w_u2i = (__half*)sym(g_w_u2i);
    __half* w_i2u = (__half*)sym(g_w_i2u);
    __half* w_su  = (__half*)sym(g_w_su);
    __half* w_si  = (__half*)sym(g_w_si);
    __half* w_f1  = (__half*)sym(g_w_f1);
    __half* w_f2  = (__half*)sym(g_w_f2);
    int* cnt_u = (int*)sym(g_cnt_u);
    int* cnt_i = (int*)sym(g_cnt_i);
    int* off_u = (int*)sym(g_off_u);
    int* off_i = (int*)sym(g_off_i);
    int* cur_u = (int*)sym(g_cur_u);
    int* cur_i = (int*)sym(g_cur_i);
    int* eid_u = (int*)sym(g_eid_u);
    int* eid_i = (int*)sym(g_eid_i);

    float* h_user = h;
    float* h_item = h + (size_t)Mu * FD;

    cudaFuncSetAttribute(gemm_mma<1>, cudaFuncAttributeMaxDynamicSharedMemorySize, 98304);
    cudaFuncSetAttribute(gemm_mma<0>, cudaFuncAttributeMaxDynamicSharedMemorySize, 65536);

    static cudaStream_t s2 = nullptr;
    static cudaEvent_t evF = nullptr, evJ = nullptr;
    if (!s2) {
        cudaStreamCreateWithFlags(&s2, cudaStreamNonBlocking);
        cudaEventCreateWithFlags(&evF, cudaEventDisableTiming);
        cudaEventCreateWithFlags(&evJ, cudaEventDisableTiming);
    }

    // ---- fork: stream B builds both CSRs --------------------------------------
    cudaEventRecord(evF, 0);
    cudaStreamWaitEvent(s2, evF, 0);
    cudaMemsetAsync(cnt_u, 0, Mu * sizeof(int), s2);
    cudaMemsetAsync(cnt_i, 0, Mi * sizeof(int), s2);
    {
        int tot = E1 + E2;
        hist2_kernel<<<(tot + 255) / 256, 256, 0, s2>>>(dst_i2u, E2, cnt_u,
                                                        dst_u2i, E1, cnt_i);
        scan_kernel<<<2, 1024, 0, s2>>>(cnt_u, off_u, cur_u, Mu,
                                        cnt_i, off_i, cur_i, Mi);
        fill2_kernel<<<(tot + 255) / 256, 256, 0, s2>>>(
            src_i2u, dst_i2u, E2, cur_u, eid_u,
            src_u2i, dst_u2i, E1, cur_i, eid_i);
    }
    cudaEventRecord(evJ, s2);

    // ---- stream A: weights, feature splits, all 4 D-GEMMs in ONE launch -------
    wtrans_all<<<dim3(128, 6), 256>>>(W_u2i, W_i2u, self_w_user, self_w_item,
                                      ffn_w1, ffn_w2,
                                      w_u2i, w_i2u, w_su, w_si, w_f1, w_f2);
    const int n4u = Mu * FD / 4, n4i = Mi * FD / 4;
    const int gx2 = (max(n4u, n4i) + 255) / 256;
    split2_kernel<<<dim3(gx2, 2), 256>>>(feat_user, fu_h, fu_l, n4u,
                                         feat_item, fi_h, fi_l, n4i);
    {
        GemmArgs a{};
        a.K = FD; a.ldC = FD; a.relu = 0;
        a.s[0] = { fu_h, fu_l, w_u2i, nullptr, nullptr, tmp_u, Mu, 0 };  // fp16 out
        a.s[1] = { fu_h, fu_l, w_su,  b_i2u,   h_user,  nullptr, Mu, 0 };
        a.s[2] = { fi_h, fi_l, w_i2u, nullptr, nullptr, tmp_i, Mi, 0 };  // fp16 out
        a.s[3] = { fi_h, fi_l, w_si,  b_u2i,   h_item,  nullptr, Mi, 0 };
        int gx = (max(Mu, Mi) + 127) / 128;
        gemm_mma<1><<<dim3(gx, 4), 256, 98304>>>(a);
    }

    // ---- join: fused gather(fp16) + LN + ReLU + residual ----------------------
    cudaStreamWaitEvent(0, evJ, 0);
    const int Mt = Mu + Mi;
    {
        dim3 lblk(32, 8);
        gather_ln_kernel<<<(Mt + 7) / 8, lblk>>>(
            h, tmp_i, tmp_u, off_u, eid_u, off_i, eid_i,
            feat_user, feat_item,
            ln_g_user, ln_b_user, ln_g_item, ln_b_item,
            hh, Mu, Mt);
    }

    // ---- FFN: both 1-term (A = hh ; A = zh) -----------------------------------
    {
        GemmArgs a{};
        a.K = FD; a.ldC = FH; a.relu = 1;
        a.s[0] = { hh, nullptr, w_f1,            ffn_b1, nullptr, zh, Mt, 0 };
        a.s[1] = { hh, nullptr, w_f1 + 128 * FD, ffn_b1, nullptr, zh, Mt, 128 };
        gemm_mma<0><<<dim3((Mt + 127) / 128, 2), 256, 65536>>>(a);
    }
    {
        GemmArgs a{};
        a.K = FH; a.ldC = FD; a.relu = 0;
        a.s[0] = { zh, nullptr, w_f2, ffn_b2, out, nullptr, Mt, 0 };
        gemm_mma<0><<<dim3((Mt + 127) / 128, 1), 256, 65536>>>(a);
    }
}

// round 14
// speedup vs baseline: 1.7744x; 1.0200x over previous
#include <cuda_runtime.h>
#include <cuda_fp16.h>
#include <cstdint>

#define FD 128
#define FH 256
#define EMAX 600000
#define NMAX 50000

// ---------------- scratch (device globals; no allocation allowed) -------------
__device__ __align__(16) __half g_tmp_u[NMAX * FD];  // feat_user @ W_u2i (fp16)
__device__ __align__(16) __half g_tmp_i[NMAX * FD];  // feat_item @ W_i2u (fp16)
__device__ float g_h[100000 * FD];                   // self transforms + msg bias (f32)
__device__ __align__(16) __half g_fu[NMAX * FD];     // feat fp16
__device__ __align__(16) __half g_fi[NMAX * FD];
__device__ __align__(16) __half g_hh[100000 * FD];
__device__ __align__(16) __half g_zh[100000 * FH];
// transposed weights fp16, layout [N][K]
__device__ __align__(16) __half g_w_u2i[FD * FD];
__device__ __align__(16) __half g_w_i2u[FD * FD];
__device__ __align__(16) __half g_w_su[FD * FD];
__device__ __align__(16) __half g_w_si[FD * FD];
__device__ __align__(16) __half g_w_f1[FH * FD];
__device__ __align__(16) __half g_w_f2[FD * FH];
// CSR scratch
__device__ int g_cnt_u[NMAX], g_cnt_i[NMAX];
__device__ int g_off_u[NMAX + 1], g_off_i[NMAX + 1];
__device__ int g_cur_u[NMAX], g_cur_i[NMAX];
__device__ int g_eid_u[EMAX], g_eid_i[EMAX];

// ---------------- PTX helpers --------------------------------------------------
__device__ __forceinline__ uint32_t smem_to_u32(const void* p) {
    uint32_t a;
    asm("{ .reg .u64 t; cvta.to.shared.u64 t, %1; cvt.u32.u64 %0, t; }"
        : "=r"(a) : "l"(p));
    return a;
}
__device__ __forceinline__ void cp16(uint32_t dst, const void* src, bool p) {
    asm volatile("cp.async.cg.shared.global [%0], [%1], 16, %2;"
                 :: "r"(dst), "l"(src), "r"(p ? 16 : 0) : "memory");
}
#define CP_COMMIT() asm volatile("cp.async.commit_group;" ::: "memory")
#define CP_WAIT1()  asm volatile("cp.async.wait_group 1;" ::: "memory")
#define CP_WAIT0()  asm volatile("cp.async.wait_group 0;" ::: "memory")

__device__ __forceinline__ void ldsm4(uint32_t a, uint32_t& r0, uint32_t& r1,
                                      uint32_t& r2, uint32_t& r3) {
    asm volatile("ldmatrix.sync.aligned.m8n8.x4.shared.b16 {%0,%1,%2,%3}, [%4];"
                 : "=r"(r0), "=r"(r1), "=r"(r2), "=r"(r3) : "r"(a));
}
__device__ __forceinline__ void mma_fp16(float* c, const uint32_t* a,
                                         uint32_t b0, uint32_t b1) {
    asm volatile("mma.sync.aligned.m16n8k16.row.col.f32.f16.f16.f32 "
                 "{%0,%1,%2,%3}, {%4,%5,%6,%7}, {%8,%9}, {%0,%1,%2,%3};"
                 : "+f"(c[0]), "+f"(c[1]), "+f"(c[2]), "+f"(c[3])
                 : "r"(a[0]), "r"(a[1]), "r"(a[2]), "r"(a[3]), "r"(b0), "r"(b1));
}

// ---------------- all-weights transpose + fp16 round ---------------------------
__global__ void __launch_bounds__(256)
wtrans_all(const float* __restrict__ W0, const float* __restrict__ W1,
           const float* __restrict__ W2, const float* __restrict__ W3,
           const float* __restrict__ W4, const float* __restrict__ W5,
           __half* __restrict__ H0, __half* __restrict__ H1,
           __half* __restrict__ H2, __half* __restrict__ H3,
           __half* __restrict__ H4, __half* __restrict__ H5)
{
    const float* W; __half* H; int K, N;
    switch (blockIdx.y) {
        case 0:  W = W0; H = H0; K = FD; N = FD; break;
        case 1:  W = W1; H = H1; K = FD; N = FD; break;
        case 2:  W = W2; H = H2; K = FD; N = FD; break;
        case 3:  W = W3; H = H3; K = FD; N = FD; break;
        case 4:  W = W4; H = H4; K = FD; N = FH; break;
        default: W = W5; H = H5; K = FH; N = FD; break;
    }
    int i = blockIdx.x * 256 + threadIdx.x;
    if (i >= K * N) return;
    int n = i / K, k = i - n * K;
    H[i] = __float2half_rn(W[(size_t)k * N + n]);
}

// ---------------- f32 -> fp16 convert, two tensors per launch ------------------
__global__ void __launch_bounds__(256)
conv2_kernel(const float* __restrict__ x0, __half* __restrict__ H0, int n40,
             const float* __restrict__ x1, __half* __restrict__ H1, int n41)
{
    const int y = blockIdx.y;
    const float* x = y ? x1 : x0;
    __half* H = y ? H1 : H0;
    const int n4 = y ? n41 : n40;
    int i = blockIdx.x * 256 + threadIdx.x;
    if (i >= n4) return;
    float4 v = *(const float4*)(x + (size_t)i * 4);
    __half2 h01 = __float22half2_rn(make_float2(v.x, v.y));
    __half2 h23 = __float22half2_rn(make_float2(v.z, v.w));
    uint2 hv = make_uint2(*(uint32_t*)&h01, *(uint32_t*)&h23);
    *(uint2*)(H + (size_t)i * 4) = hv;
}

// ---------------- CSR build ----------------------------------------------------
__global__ void __launch_bounds__(256)
hist2_kernel(const int* __restrict__ dst_iu, int E2, int* __restrict__ cnt_u,
             const int* __restrict__ dst_ui, int E1, int* __restrict__ cnt_i)
{
    int i = blockIdx.x * 256 + threadIdx.x;
    if (i < E2) atomicAdd(&cnt_u[__ldg(&dst_iu[i])], 1);
    else if (i - E2 < E1) atomicAdd(&cnt_i[__ldg(&dst_ui[i - E2])], 1);
}

__global__ void __launch_bounds__(1024)
scan_kernel(const int* __restrict__ cnt0, int* __restrict__ off0, int* __restrict__ cur0, int n0,
            const int* __restrict__ cnt1, int* __restrict__ off1, int* __restrict__ cur1, int n1)
{
    const int* cnt = blockIdx.x ? cnt1 : cnt0;
    int* off = blockIdx.x ? off1 : off0;
    int* cur = blockIdx.x ? cur1 : cur0;
    const int n = blockIdx.x ? n1 : n0;

    __shared__ int sa[1024], sb[1024];
    __shared__ int carry;
    int tid = threadIdx.x;
    if (tid == 0) { carry = 0; off[0] = 0; }
    __syncthreads();

    for (int base = 0; base < n; base += 1024) {
        int v = (base + tid < n) ? cnt[base + tid] : 0;
        int* A = sa; int* B = sb;
        A[tid] = v; __syncthreads();
        #pragma unroll
        for (int d = 1; d < 1024; d <<= 1) {
            B[tid] = A[tid] + ((tid >= d) ? A[tid - d] : 0);
            __syncthreads();
            int* t = A; A = B; B = t;
        }
        int inc = A[tid] + carry;
        if (base + tid < n) { off[base + tid + 1] = inc; cur[base + tid] = inc - v; }
        int blocksum = A[1023];
        __syncthreads();
        if (tid == 0) carry += blocksum;
        __syncthreads();
    }
}

__global__ void __launch_bounds__(256)
fill2_kernel(const int* __restrict__ src_iu, const int* __restrict__ dst_iu, int E2,
             int* __restrict__ cur_u, int* __restrict__ eid_u,
             const int* __restrict__ src_ui, const int* __restrict__ dst_ui, int E1,
             int* __restrict__ cur_i, int* __restrict__ eid_i)
{
    int i = blockIdx.x * 256 + threadIdx.x;
    if (i < E2) {
        int p = atomicAdd(&cur_u[__ldg(&dst_iu[i])], 1);
        eid_u[p] = __ldg(&src_iu[i]);
    } else if (i - E2 < E1) {
        int e = i - E2;
        int p = atomicAdd(&cur_i[__ldg(&dst_ui[e])], 1);
        eid_i[p] = __ldg(&src_ui[e]);
    }
}

// ---------------- tensor-core GEMM (mma.sync fp16, 1-term A) -------------------
// 128x128 C tile; grid.y selects one of up to 4 GemmSets.
// smem: 2 stages x 32KB { A 16K | B 16K }, 128B rows, XOR swizzle.
struct GemmSet {
    const __half* Ah;
    const __half* B;  const float* bias;
    float* outF; __half* outH;
    int M; int colOff;
};
struct GemmArgs { GemmSet s[4]; int K; int ldC; int relu; };

__global__ void __launch_bounds__(256)
gemm_mma(GemmArgs args)
{
    constexpr uint32_t STAGE = 32768;
    constexpr uint32_t BOFF  = 16384;

    extern __shared__ char smem[];
    const uint32_t smBase = smem_to_u32(smem);
    const int tid = threadIdx.x;
    const int lane = tid & 31, wid = tid >> 5;

    const GemmSet s = args.s[blockIdx.y];
    const int M = s.M;
    const int K = args.K, ldC = args.ldC;
    const int rowBase = blockIdx.x * 128;
    if (rowBase >= M) return;
    const int nc = K >> 6;

    const int ir = tid >> 1;
    const int ikh = tid & 1;
    const bool aOk = (rowBase + ir) < M;
    const size_t aBase = (size_t)(aOk ? rowBase + ir : 0) * K;
    const size_t bBase = (size_t)ir * K;

    auto issue = [&](int c, int st_i) {
        uint32_t st = smBase + st_i * STAGE;
        #pragma unroll
        for (int i = 0; i < 4; i++) {
            int byteoff = ikh * 64 + i * 16;
            uint32_t doff = (uint32_t)ir * 128 + (uint32_t)(byteoff ^ ((ir & 7) << 4));
            int kOff = c * 64 + (byteoff >> 1);
            cp16(st + doff, s.Ah + aBase + kOff, aOk);
            cp16(st + BOFF + doff, s.B + bBase + kOff, true);
        }
        CP_COMMIT();
    };

    const int m0w = (wid & 3) * 32;
    const int n0w = (wid >> 2) * 64;
    const int rA = lane & 15;
    const uint32_t kxA = (uint32_t)((lane >> 4) << 4);
    const uint32_t aoff = (uint32_t)(m0w + rA) * 128;
    const uint32_t axor = (uint32_t)((rA & 7) << 4);
    const int rB = (lane & 7) + ((lane >> 4) << 3);
    const uint32_t kxB = (uint32_t)((lane & 8) << 1);
    const uint32_t bxor = (uint32_t)((rB & 7) << 4);

    float acc[2][8][4];
    #pragma unroll
    for (int a = 0; a < 2; a++)
        #pragma unroll
        for (int b = 0; b < 8; b++)
            #pragma unroll
            for (int c = 0; c < 4; c++) acc[a][b][c] = 0.f;

    issue(0, 0);
    if (nc > 1) issue(1, 1);

    for (int c = 0; c < nc; c++) {
        if (c + 1 < nc) CP_WAIT1(); else CP_WAIT0();
        __syncthreads();

        const int st_i = c & 1;
        const uint32_t As = smBase + st_i * STAGE;
        const uint32_t Bs = As + BOFF;

        #pragma unroll
        for (int kk4 = 0; kk4 < 4; kk4++) {
            const uint32_t kb = (uint32_t)kk4 * 32;
            uint32_t ah[2][4];
            #pragma unroll
            for (int mt = 0; mt < 2; mt++) {
                uint32_t ad = aoff + (uint32_t)mt * 2048 + ((kb + kxA) ^ axor);
                ldsm4(As + ad, ah[mt][0], ah[mt][1], ah[mt][2], ah[mt][3]);
            }
            #pragma unroll
            for (int ng = 0; ng < 4; ng++) {
                uint32_t bd = (uint32_t)(n0w + ng * 16 + rB) * 128 + ((kb + kxB) ^ bxor);
                uint32_t bh[4];
                ldsm4(Bs + bd, bh[0], bh[1], bh[2], bh[3]);
                #pragma unroll
                for (int mt = 0; mt < 2; mt++) {
                    mma_fp16(acc[mt][ng * 2 + 0], ah[mt], bh[0], bh[1]);
                    mma_fp16(acc[mt][ng * 2 + 1], ah[mt], bh[2], bh[3]);
                }
            }
        }
        __syncthreads();
        if (c + 2 < nc) issue(c + 2, st_i);
    }

    const int g = lane >> 2, tig = lane & 3;
    #pragma unroll
    for (int mt = 0; mt < 2; mt++) {
        const int r0 = rowBase + m0w + mt * 16 + g;
        #pragma unroll
        for (int t = 0; t < 8; t++) {
            const int col = s.colOff + n0w + t * 8 + tig * 2;
            float b0 = 0.f, b1 = 0.f;
            if (s.bias) { b0 = __ldg(s.bias + col); b1 = __ldg(s.bias + col + 1); }
            float v00 = acc[mt][t][0] + b0, v01 = acc[mt][t][1] + b1;
            float v10 = acc[mt][t][2] + b0, v11 = acc[mt][t][3] + b1;
            if (args.relu) {
                v00 = fmaxf(v00, 0.f); v01 = fmaxf(v01, 0.f);
                v10 = fmaxf(v10, 0.f); v11 = fmaxf(v11, 0.f);
            }
            if (s.outF) {
                if (r0 < M)     *(float2*)&s.outF[(size_t)r0 * ldC + col]       = make_float2(v00, v01);
                if (r0 + 8 < M) *(float2*)&s.outF[(size_t)(r0 + 8) * ldC + col] = make_float2(v10, v11);
            } else {
                if (r0 < M) {
                    __half2 hv = __float22half2_rn(make_float2(v00, v01));
                    *(__half2*)&s.outH[(size_t)r0 * ldC + col] = hv;
                }
                if (r0 + 8 < M) {
                    __half2 hv = __float22half2_rn(make_float2(v10, v11));
                    *(__half2*)&s.outH[(size_t)(r0 + 8) * ldC + col] = hv;
                }
            }
        }
    }
}

// ---------------- fused gather(fp16 msgs) + LN + ReLU + residual ---------------
__global__ void __launch_bounds__(256)
gather_ln_kernel(const float* __restrict__ hself,
                 const __half* __restrict__ tmp_i, const __half* __restrict__ tmp_u,
                 const int* __restrict__ off_u, const int* __restrict__ eid_u,
                 const int* __restrict__ off_i, const int* __restrict__ eid_i,
                 const float* __restrict__ fu, const float* __restrict__ fi,
                 const float* __restrict__ gu, const float* __restrict__ bu,
                 const float* __restrict__ gi, const float* __restrict__ bi,
                 __half* __restrict__ outH,
                 int Mu, int Mt)
{
    int row = blockIdx.x * 8 + threadIdx.y;
    if (row >= Mt) return;
    int lane = threadIdx.x;
    const bool isU = row < Mu;
    const int r = isU ? row : row - Mu;
    const int* off = isU ? off_u : off_i;
    const int* eid = isU ? eid_u : eid_i;
    const __half* tmp = isU ? tmp_i : tmp_u;
    const float* feat = isU ? fu + (size_t)r * FD : fi + (size_t)r * FD;
    const float* g = isU ? gu : gi;
    const float* b = isU ? bu : bi;

    const int s0 = __ldg(&off[r]);
    const int s1 = __ldg(&off[r + 1]);

    float4 acc = *(const float4*)&hself[(size_t)row * FD + lane * 4];

    for (int base = s0; base < s1; base += 32) {
        int idx = (base + lane < s1) ? __ldg(&eid[base + lane]) : 0;
        int m = min(32, s1 - base);
        #pragma unroll 4
        for (int k = 0; k < m; k++) {
            int id = __shfl_sync(0xffffffffu, idx, k);
            uint2 raw = *(const uint2*)&tmp[(size_t)id * FD + lane * 4];
            float2 p0 = __half22float2(*(__half2*)&raw.x);
            float2 p1 = __half22float2(*(__half2*)&raw.y);
            acc.x += p0.x; acc.y += p0.y; acc.z += p1.x; acc.w += p1.y;
        }
    }

    float s = acc.x + acc.y + acc.z + acc.w;
    #pragma unroll
    for (int off2 = 16; off2 > 0; off2 >>= 1) s += __shfl_xor_sync(0xffffffffu, s, off2);
    float mean = s * (1.0f / FD);
    float dx = acc.x - mean, dy = acc.y - mean, dz = acc.z - mean, dw = acc.w - mean;
    float q = dx * dx + dy * dy + dz * dz + dw * dw;
    #pragma unroll
    for (int off2 = 16; off2 > 0; off2 >>= 1) q += __shfl_xor_sync(0xffffffffu, q, off2);
    float rstd = rsqrtf(q * (1.0f / FD) + 1e-5f);

    float4 gv = *(const float4*)&g[lane * 4];
    float4 bv = *(const float4*)&b[lane * 4];
    float4 fv = *(const float4*)&feat[lane * 4];
    float4 o;
    o.x = fmaxf(dx * rstd * gv.x + bv.x, 0.f) + fv.x;
    o.y = fmaxf(dy * rstd * gv.y + bv.y, 0.f) + fv.y;
    o.z = fmaxf(dz * rstd * gv.z + bv.z, 0.f) + fv.z;
    o.w = fmaxf(dw * rstd * gv.w + bv.w, 0.f) + fv.w;

    __half2 h01 = __float22half2_rn(make_float2(o.x, o.y));
    __half2 h23 = __float22half2_rn(make_float2(o.z, o.w));
    uint2 hv = make_uint2(*(uint32_t*)&h01, *(uint32_t*)&h23);
    *(uint2*)&outH[(size_t)row * FD + lane * 4] = hv;
}

// ---------------- launch ------------------------------------------------------
extern "C" void kernel_launch(void* const* d_in, const int* in_sizes, int n_in,
                              void* d_out, int out_size)
{
    const float* feat_user   = (const float*)d_in[0];
    const float* feat_item   = (const float*)d_in[1];
    const float* W_u2i       = (const float*)d_in[2];
    const float* b_u2i       = (const float*)d_in[3];
    const float* W_i2u       = (const float*)d_in[4];
    const float* b_i2u       = (const float*)d_in[5];
    const float* self_w_user = (const float*)d_in[6];
    const float* self_w_item = (const float*)d_in[7];
    const float* ln_g_user   = (const float*)d_in[8];
    const float* ln_b_user   = (const float*)d_in[9];
    const float* ln_g_item   = (const float*)d_in[10];
    const float* ln_b_item   = (const float*)d_in[11];
    const float* ffn_w1      = (const float*)d_in[12];
    const float* ffn_b1      = (const float*)d_in[13];
    const float* ffn_w2      = (const float*)d_in[14];
    const float* ffn_b2      = (const float*)d_in[15];
    const int*   src_u2i     = (const int*)d_in[16];
    const int*   dst_u2i     = (const int*)d_in[17];
    const int*   src_i2u     = (const int*)d_in[18];
    const int*   dst_i2u     = (const int*)d_in[19];

    const int Mu = in_sizes[0] / FD;
    const int Mi = in_sizes[1] / FD;
    const int E1 = in_sizes[16];
    const int E2 = in_sizes[18];
    float* out = (float*)d_out;

    auto sym = [](const void* s) { void* p; cudaGetSymbolAddress(&p, s); return p; };
    __half* tmp_u = (__half*)sym(g_tmp_u);
    __half* tmp_i = (__half*)sym(g_tmp_i);
    float* h      = (float*)sym(g_h);
    __half* fu = (__half*)sym(g_fu);
    __half* fi = (__half*)sym(g_fi);
    __half* hh = (__half*)sym(g_hh);
    __half* zh = (__half*)sym(g_zh);
    __half* w_u2i = (__half*)sym(g_w_u2i);
    __half* w_i2u = (__half*)sym(g_w_i2u);
    __half* w_su  = (__half*)sym(g_w_su);
    __half* w_si  = (__half*)sym(g_w_si);
    __half* w_f1  = (__half*)sym(g_w_f1);
    __half* w_f2  = (__half*)sym(g_w_f2);
    int* cnt_u = (int*)sym(g_cnt_u);
    int* cnt_i = (int*)sym(g_cnt_i);
    int* off_u = (int*)sym(g_off_u);
    int* off_i = (int*)sym(g_off_i);
    int* cur_u = (int*)sym(g_cur_u);
    int* cur_i = (int*)sym(g_cur_i);
    int* eid_u = (int*)sym(g_eid_u);
    int* eid_i = (int*)sym(g_eid_i);

    float* h_user = h;
    float* h_item = h + (size_t)Mu * FD;

    cudaFuncSetAttribute(gemm_mma, cudaFuncAttributeMaxDynamicSharedMemorySize, 65536);

    static cudaStream_t s2 = nullptr;
    static cudaEvent_t evF = nullptr, evJ = nullptr;
    if (!s2) {
        cudaStreamCreateWithFlags(&s2, cudaStreamNonBlocking);
        cudaEventCreateWithFlags(&evF, cudaEventDisableTiming);
        cudaEventCreateWithFlags(&evJ, cudaEventDisableTiming);
    }

    // ---- fork: stream B builds both CSRs --------------------------------------
    cudaEventRecord(evF, 0);
    cudaStreamWaitEvent(s2, evF, 0);
    cudaMemsetAsync(cnt_u, 0, Mu * sizeof(int), s2);
    cudaMemsetAsync(cnt_i, 0, Mi * sizeof(int), s2);
    {
        int tot = E1 + E2;
        hist2_kernel<<<(tot + 255) / 256, 256, 0, s2>>>(dst_i2u, E2, cnt_u,
                                                        dst_u2i, E1, cnt_i);
        scan_kernel<<<2, 1024, 0, s2>>>(cnt_u, off_u, cur_u, Mu,
                                        cnt_i, off_i, cur_i, Mi);
        fill2_kernel<<<(tot + 255) / 256, 256, 0, s2>>>(
            src_i2u, dst_i2u, E2, cur_u, eid_u,
            src_u2i, dst_u2i, E1, cur_i, eid_i);
    }
    cudaEventRecord(evJ, s2);

    // ---- stream A: weights, feature converts, all 4 D-GEMMs in ONE launch -----
    wtrans_all<<<dim3(128, 6), 256>>>(W_u2i, W_i2u, self_w_user, self_w_item,
                                      ffn_w1, ffn_w2,
                                      w_u2i, w_i2u, w_su, w_si, w_f1, w_f2);
    const int n4u = Mu * FD / 4, n4i = Mi * FD / 4;
    const int gx2 = (max(n4u, n4i) + 255) / 256;
    conv2_kernel<<<dim3(gx2, 2), 256>>>(feat_user, fu, n4u, feat_item, fi, n4i);
    {
        GemmArgs a{};
        a.K = FD; a.ldC = FD; a.relu = 0;
        a.s[0] = { fu, w_u2i, nullptr, nullptr, tmp_u, Mu, 0 };
        a.s[1] = { fu, w_su,  b_i2u,   h_user,  nullptr, Mu, 0 };
        a.s[2] = { fi, w_i2u, nullptr, nullptr, tmp_i, Mi, 0 };
        a.s[3] = { fi, w_si,  b_u2i,   h_item,  nullptr, Mi, 0 };
        int gx = (max(Mu, Mi) + 127) / 128;
        gemm_mma<<<dim3(gx, 4), 256, 65536>>>(a);
    }

    // ---- join: fused gather(fp16) + LN + ReLU + residual ----------------------
    cudaStreamWaitEvent(0, evJ, 0);
    const int Mt = Mu + Mi;
    {
        dim3 lblk(32, 8);
        gather_ln_kernel<<<(Mt + 7) / 8, lblk>>>(
            h, tmp_i, tmp_u, off_u, eid_u, off_i, eid_i,
            feat_user, feat_item,
            ln_g_user, ln_b_user, ln_g_item, ln_b_item,
            hh, Mu, Mt);
    }

    // ---- FFN ------------------------------------------------------------------
    {
        GemmArgs a{};
        a.K = FD; a.ldC = FH; a.relu = 1;
        a.s[0] = { hh, w_f1,            ffn_b1, nullptr, zh, Mt, 0 };
        a.s[1] = { hh, w_f1 + 128 * FD, ffn_b1, nullptr, zh, Mt, 128 };
        gemm_mma<<<dim3((Mt + 127) / 128, 2), 256, 65536>>>(a);
    }
    {
        GemmArgs a{};
        a.K = FH; a.ldC = FD; a.relu = 0;
        a.s[0] = { zh, w_f2, ffn_b2, out, nullptr, Mt, 0 };
        gemm_mma<<<dim3((Mt + 127) / 128, 1), 256, 65536>>>(a);
    }
}

// round 17
// speedup vs baseline: 1.9466x; 1.0971x over previous
#include <cuda_runtime.h>
#include <cuda_fp16.h>
#include <cstdint>

#define FD 128
#define FH 256
#define EMAX 600000
#define NMAX 50000

// ---------------- scratch (device globals; no allocation allowed) -------------
__device__ __align__(16) __half g_tmp_u[NMAX * FD];  // feat_user @ W_u2i (fp16)
__device__ __align__(16) __half g_tmp_i[NMAX * FD];  // feat_item @ W_i2u (fp16)
__device__ float g_h[100000 * FD];                   // self transforms + msg bias (f32)
__device__ __align__(16) __half g_fu[NMAX * FD];     // feat fp16
__device__ __align__(16) __half g_fi[NMAX * FD];
__device__ __align__(16) __half g_hh[100000 * FD];
// transposed weights fp16, layout [N][K]
__device__ __align__(16) __half g_w_u2i[FD * FD];
__device__ __align__(16) __half g_w_i2u[FD * FD];
__device__ __align__(16) __half g_w_su[FD * FD];
__device__ __align__(16) __half g_w_si[FD * FD];
__device__ __align__(16) __half g_w_f1[FH * FD];
__device__ __align__(16) __half g_w_f2[FD * FH];
// CSR scratch
__device__ int g_cnt_u[NMAX], g_cnt_i[NMAX];
__device__ int g_off_u[NMAX + 1], g_off_i[NMAX + 1];
__device__ int g_cur_u[NMAX], g_cur_i[NMAX];
__device__ int g_eid_u[EMAX], g_eid_i[EMAX];

// ---------------- PTX helpers --------------------------------------------------
__device__ __forceinline__ uint32_t smem_to_u32(const void* p) {
    uint32_t a;
    asm("{ .reg .u64 t; cvta.to.shared.u64 t, %1; cvt.u32.u64 %0, t; }"
        : "=r"(a) : "l"(p));
    return a;
}
__device__ __forceinline__ void cp16(uint32_t dst, const void* src, bool p) {
    asm volatile("cp.async.cg.shared.global [%0], [%1], 16, %2;"
                 :: "r"(dst), "l"(src), "r"(p ? 16 : 0) : "memory");
}
#define CP_COMMIT() asm volatile("cp.async.commit_group;" ::: "memory")
#define CP_WAIT1()  asm volatile("cp.async.wait_group 1;" ::: "memory")
#define CP_WAIT0()  asm volatile("cp.async.wait_group 0;" ::: "memory")

__device__ __forceinline__ void ldsm4(uint32_t a, uint32_t& r0, uint32_t& r1,
                                      uint32_t& r2, uint32_t& r3) {
    asm volatile("ldmatrix.sync.aligned.m8n8.x4.shared.b16 {%0,%1,%2,%3}, [%4];"
                 : "=r"(r0), "=r"(r1), "=r"(r2), "=r"(r3) : "r"(a));
}
__device__ __forceinline__ void mma_fp16(float* c, const uint32_t* a,
                                         uint32_t b0, uint32_t b1) {
    asm volatile("mma.sync.aligned.m16n8k16.row.col.f32.f16.f16.f32 "
                 "{%0,%1,%2,%3}, {%4,%5,%6,%7}, {%8,%9}, {%0,%1,%2,%3};"
                 : "+f"(c[0]), "+f"(c[1]), "+f"(c[2]), "+f"(c[3])
                 : "r"(a[0]), "r"(a[1]), "r"(a[2]), "r"(a[3]), "r"(b0), "r"(b1));
}

// ---------------- all-weights transpose + fp16 round ---------------------------
__global__ void __launch_bounds__(256)
wtrans_all(const float* __restrict__ W0, const float* __restrict__ W1,
           const float* __restrict__ W2, const float* __restrict__ W3,
           const float* __restrict__ W4, const float* __restrict__ W5,
           __half* __restrict__ H0, __half* __restrict__ H1,
           __half* __restrict__ H2, __half* __restrict__ H3,
           __half* __restrict__ H4, __half* __restrict__ H5)
{
    const float* W; __half* H; int K, N;
    switch (blockIdx.y) {
        case 0:  W = W0; H = H0; K = FD; N = FD; break;
        case 1:  W = W1; H = H1; K = FD; N = FD; break;
        case 2:  W = W2; H = H2; K = FD; N = FD; break;
        case 3:  W = W3; H = H3; K = FD; N = FD; break;
        case 4:  W = W4; H = H4; K = FD; N = FH; break;
        default: W = W5; H = H5; K = FH; N = FD; break;
    }
    int i = blockIdx.x * 256 + threadIdx.x;
    if (i >= K * N) return;
    int n = i / K, k = i - n * K;
    H[i] = __float2half_rn(W[(size_t)k * N + n]);
}

// ---------------- f32 -> fp16 convert, two tensors per launch ------------------
__global__ void __launch_bounds__(256)
conv2_kernel(const float* __restrict__ x0, __half* __restrict__ H0, int n40,
             const float* __restrict__ x1, __half* __restrict__ H1, int n41)
{
    const int y = blockIdx.y;
    const float* x = y ? x1 : x0;
    __half* H = y ? H1 : H0;
    const int n4 = y ? n41 : n40;
    int i = blockIdx.x * 256 + threadIdx.x;
    if (i >= n4) return;
    float4 v = *(const float4*)(x + (size_t)i * 4);
    __half2 h01 = __float22half2_rn(make_float2(v.x, v.y));
    __half2 h23 = __float22half2_rn(make_float2(v.z, v.w));
    uint2 hv = make_uint2(*(uint32_t*)&h01, *(uint32_t*)&h23);
    *(uint2*)(H + (size_t)i * 4) = hv;
}

// ---------------- CSR build ----------------------------------------------------
__global__ void __launch_bounds__(256)
hist2_kernel(const int* __restrict__ dst_iu, int E2, int* __restrict__ cnt_u,
             const int* __restrict__ dst_ui, int E1, int* __restrict__ cnt_i)
{
    int i = blockIdx.x * 256 + threadIdx.x;
    if (i < E2) atomicAdd(&cnt_u[__ldg(&dst_iu[i])], 1);
    else if (i - E2 < E1) atomicAdd(&cnt_i[__ldg(&dst_ui[i - E2])], 1);
}

__global__ void __launch_bounds__(1024)
scan_kernel(const int* __restrict__ cnt0, int* __restrict__ off0, int* __restrict__ cur0, int n0,
            const int* __restrict__ cnt1, int* __restrict__ off1, int* __restrict__ cur1, int n1)
{
    const int* cnt = blockIdx.x ? cnt1 : cnt0;
    int* off = blockIdx.x ? off1 : off0;
    int* cur = blockIdx.x ? cur1 : cur0;
    const int n = blockIdx.x ? n1 : n0;

    __shared__ int sa[1024], sb[1024];
    __shared__ int carry;
    int tid = threadIdx.x;
    if (tid == 0) { carry = 0; off[0] = 0; }
    __syncthreads();

    for (int base = 0; base < n; base += 1024) {
        int v = (base + tid < n) ? cnt[base + tid] : 0;
        int* A = sa; int* B = sb;
        A[tid] = v; __syncthreads();
        #pragma unroll
        for (int d = 1; d < 1024; d <<= 1) {
            B[tid] = A[tid] + ((tid >= d) ? A[tid - d] : 0);
            __syncthreads();
            int* t = A; A = B; B = t;
        }
        int inc = A[tid] + carry;
        if (base + tid < n) { off[base + tid + 1] = inc; cur[base + tid] = inc - v; }
        int blocksum = A[1023];
        __syncthreads();
        if (tid == 0) carry += blocksum;
        __syncthreads();
    }
}

__global__ void __launch_bounds__(256)
fill2_kernel(const int* __restrict__ src_iu, const int* __restrict__ dst_iu, int E2,
             int* __restrict__ cur_u, int* __restrict__ eid_u,
             const int* __restrict__ src_ui, const int* __restrict__ dst_ui, int E1,
             int* __restrict__ cur_i, int* __restrict__ eid_i)
{
    int i = blockIdx.x * 256 + threadIdx.x;
    if (i < E2) {
        int p = atomicAdd(&cur_u[__ldg(&dst_iu[i])], 1);
        eid_u[p] = __ldg(&src_iu[i]);
    } else if (i - E2 < E1) {
        int e = i - E2;
        int p = atomicAdd(&cur_i[__ldg(&dst_ui[e])], 1);
        eid_i[p] = __ldg(&src_ui[e]);
    }
}

// ---------------- tensor-core GEMM (mma.sync fp16, 1-term A) -------------------
struct GemmSet {
    const __half* Ah;
    const __half* B;  const float* bias;
    float* outF; __half* outH;
    int M; int colOff;
};
struct GemmArgs { GemmSet s[4]; int K; int ldC; int relu; };

__global__ void __launch_bounds__(256)
gemm_mma(GemmArgs args)
{
    constexpr uint32_t STAGE = 32768;
    constexpr uint32_t BOFF  = 16384;

    extern __shared__ char smem[];
    const uint32_t smBase = smem_to_u32(smem);
    const int tid = threadIdx.x;
    const int lane = tid & 31, wid = tid >> 5;

    const GemmSet s = args.s[blockIdx.y];
    const int M = s.M;
    const int K = args.K, ldC = args.ldC;
    const int rowBase = blockIdx.x * 128;
    if (rowBase >= M) return;
    const int nc = K >> 6;

    const int ir = tid >> 1;
    const int ikh = tid & 1;
    const bool aOk = (rowBase + ir) < M;
    const size_t aBase = (size_t)(aOk ? rowBase + ir : 0) * K;
    const size_t bBase = (size_t)ir * K;

    auto issue = [&](int c, int st_i) {
        uint32_t st = smBase + st_i * STAGE;
        #pragma unroll
        for (int i = 0; i < 4; i++) {
            int byteoff = ikh * 64 + i * 16;
            uint32_t doff = (uint32_t)ir * 128 + (uint32_t)(byteoff ^ ((ir & 7) << 4));
            int kOff = c * 64 + (byteoff >> 1);
            cp16(st + doff, s.Ah + aBase + kOff, aOk);
            cp16(st + BOFF + doff, s.B + bBase + kOff, true);
        }
        CP_COMMIT();
    };

    const int m0w = (wid & 3) * 32;
    const int n0w = (wid >> 2) * 64;
    const int rA = lane & 15;
    const uint32_t kxA = (uint32_t)((lane >> 4) << 4);
    const uint32_t aoff = (uint32_t)(m0w + rA) * 128;
    const uint32_t axor = (uint32_t)((rA & 7) << 4);
    const int rB = (lane & 7) + ((lane >> 4) << 3);
    const uint32_t kxB = (uint32_t)((lane & 8) << 1);
    const uint32_t bxor = (uint32_t)((rB & 7) << 4);

    float acc[2][8][4];
    #pragma unroll
    for (int a = 0; a < 2; a++)
        #pragma unroll
        for (int b = 0; b < 8; b++)
            #pragma unroll
            for (int c = 0; c < 4; c++) acc[a][b][c] = 0.f;

    issue(0, 0);
    if (nc > 1) issue(1, 1);

    for (int c = 0; c < nc; c++) {
        if (c + 1 < nc) CP_WAIT1(); else CP_WAIT0();
        __syncthreads();

        const int st_i = c & 1;
        const uint32_t As = smBase + st_i * STAGE;
        const uint32_t Bs = As + BOFF;

        #pragma unroll
        for (int kk4 = 0; kk4 < 4; kk4++) {
            const uint32_t kb = (uint32_t)kk4 * 32;
            uint32_t ah[2][4];
            #pragma unroll
            for (int mt = 0; mt < 2; mt++) {
                uint32_t ad = aoff + (uint32_t)mt * 2048 + ((kb + kxA) ^ axor);
                ldsm4(As + ad, ah[mt][0], ah[mt][1], ah[mt][2], ah[mt][3]);
            }
            #pragma unroll
            for (int ng = 0; ng < 4; ng++) {
                uint32_t bd = (uint32_t)(n0w + ng * 16 + rB) * 128 + ((kb + kxB) ^ bxor);
                uint32_t bh[4];
                ldsm4(Bs + bd, bh[0], bh[1], bh[2], bh[3]);
                #pragma unroll
                for (int mt = 0; mt < 2; mt++) {
                    mma_fp16(acc[mt][ng * 2 + 0], ah[mt], bh[0], bh[1]);
                    mma_fp16(acc[mt][ng * 2 + 1], ah[mt], bh[2], bh[3]);
                }
            }
        }
        __syncthreads();
        if (c + 2 < nc) issue(c + 2, st_i);
    }

    const int g = lane >> 2, tig = lane & 3;
    #pragma unroll
    for (int mt = 0; mt < 2; mt++) {
        const int r0 = rowBase + m0w + mt * 16 + g;
        #pragma unroll
        for (int t = 0; t < 8; t++) {
            const int col = s.colOff + n0w + t * 8 + tig * 2;
            float b0 = 0.f, b1 = 0.f;
            if (s.bias) { b0 = __ldg(s.bias + col); b1 = __ldg(s.bias + col + 1); }
            float v00 = acc[mt][t][0] + b0, v01 = acc[mt][t][1] + b1;
            float v10 = acc[mt][t][2] + b0, v11 = acc[mt][t][3] + b1;
            if (args.relu) {
                v00 = fmaxf(v00, 0.f); v01 = fmaxf(v01, 0.f);
                v10 = fmaxf(v10, 0.f); v11 = fmaxf(v11, 0.f);
            }
            if (s.outF) {
                if (r0 < M)     *(float2*)&s.outF[(size_t)r0 * ldC + col]       = make_float2(v00, v01);
                if (r0 + 8 < M) *(float2*)&s.outF[(size_t)(r0 + 8) * ldC + col] = make_float2(v10, v11);
            } else {
                if (r0 < M) {
                    __half2 hv = __float22half2_rn(make_float2(v00, v01));
                    *(__half2*)&s.outH[(size_t)r0 * ldC + col] = hv;
                }
                if (r0 + 8 < M) {
                    __half2 hv = __float22half2_rn(make_float2(v10, v11));
                    *(__half2*)&s.outH[(size_t)(r0 + 8) * ldC + col] = hv;
                }
            }
        }
    }
}

// ---------------- fused FFN: out = relu(h@W1+b1)@W2+b2 -------------------------
// smem: A(hh tile) 2x16K @0 ; z 4x16K @32768 ; B stages 2x16K @98304. 128KB.
__global__ void __launch_bounds__(256)
ffn_fused(const __half* __restrict__ hh,
          const __half* __restrict__ w1, const float* __restrict__ b1,
          const __half* __restrict__ w2, const float* __restrict__ b2,
          float* __restrict__ out, int M)
{
    extern __shared__ char smem[];
    const uint32_t smBase = smem_to_u32(smem);
    const uint32_t ZB = smBase + 32768;
    const uint32_t BB = smBase + 98304;
    const int tid = threadIdx.x;
    const int lane = tid & 31, wid = tid >> 5;
    const int rowBase = blockIdx.x * 128;
    if (rowBase >= M) return;

    const int ir = tid >> 1;
    const int ikh = tid & 1;
    const bool aOk = (rowBase + ir) < M;
    const size_t aRow = (size_t)(aOk ? rowBase + ir : 0) * FD;

    // A: load both K-chunks of hh tile (groups 1,2)
    #pragma unroll
    for (int c = 0; c < 2; c++) {
        #pragma unroll
        for (int i = 0; i < 4; i++) {
            int byteoff = ikh * 64 + i * 16;
            uint32_t doff = (uint32_t)ir * 128 + (uint32_t)(byteoff ^ ((ir & 7) << 4));
            cp16(smBase + c * 16384 + doff, hh + aRow + c * 64 + (byteoff >> 1), aOk);
        }
        CP_COMMIT();
    }
    // B chunk q of W1 (q = nhalf*2 + kchunk), K=128
    auto issueB1 = [&](int q, int st_i) {
        const __half* src = w1 + (size_t)((q >> 1) * 128 + ir) * FD + (q & 1) * 64;
        #pragma unroll
        for (int i = 0; i < 4; i++) {
            int byteoff = ikh * 64 + i * 16;
            uint32_t doff = (uint32_t)ir * 128 + (uint32_t)(byteoff ^ ((ir & 7) << 4));
            cp16(BB + st_i * 16384 + doff, src + (byteoff >> 1), true);
        }
        CP_COMMIT();
    };
    // B chunk q of W2, K=256
    auto issueB2 = [&](int q, int st_i) {
        const __half* src = w2 + (size_t)ir * FH + q * 64;
        #pragma unroll
        for (int i = 0; i < 4; i++) {
            int byteoff = ikh * 64 + i * 16;
            uint32_t doff = (uint32_t)ir * 128 + (uint32_t)(byteoff ^ ((ir & 7) << 4));
            cp16(BB + st_i * 16384 + doff, src + (byteoff >> 1), true);
        }
        CP_COMMIT();
    };

    const int m0w = (wid & 3) * 32;
    const int n0w = (wid >> 2) * 64;
    const int rA = lane & 15;
    const uint32_t kxA = (uint32_t)((lane >> 4) << 4);
    const uint32_t aoff = (uint32_t)(m0w + rA) * 128;
    const uint32_t axor = (uint32_t)((rA & 7) << 4);
    const int rB = (lane & 7) + ((lane >> 4) << 3);
    const uint32_t kxB = (uint32_t)((lane & 8) << 1);
    const uint32_t bxor = (uint32_t)((rB & 7) << 4);
    const int g = lane >> 2, tig = lane & 3;

    float acc[2][8][4];

    issueB1(0, 0);
    issueB1(1, 1);

    // ---- phase 1: z = relu(h @ W1 + b1), two 128-col halves -------------------
    #pragma unroll
    for (int j = 0; j < 2; j++) {
        #pragma unroll
        for (int a = 0; a < 2; a++)
            #pragma unroll
            for (int b = 0; b < 8; b++)
                #pragma unroll
                for (int c = 0; c < 4; c++) acc[a][b][c] = 0.f;

        #pragma unroll
        for (int c = 0; c < 2; c++) {
            int q = j * 2 + c;
            if (q < 3) CP_WAIT1(); else CP_WAIT0();
            __syncthreads();
            const uint32_t As = smBase + c * 16384;
            const uint32_t Bs = BB + (q & 1) * 16384;
            #pragma unroll
            for (int kk4 = 0; kk4 < 4; kk4++) {
                const uint32_t kb = (uint32_t)kk4 * 32;
                uint32_t ah[2][4];
                #pragma unroll
                for (int mt = 0; mt < 2; mt++) {
                    uint32_t ad = aoff + (uint32_t)mt * 2048 + ((kb + kxA) ^ axor);
                    ldsm4(As + ad, ah[mt][0], ah[mt][1], ah[mt][2], ah[mt][3]);
                }
                #pragma unroll
                for (int ng = 0; ng < 4; ng++) {
                    uint32_t bd = (uint32_t)(n0w + ng * 16 + rB) * 128 + ((kb + kxB) ^ bxor);
                    uint32_t bh[4];
                    ldsm4(Bs + bd, bh[0], bh[1], bh[2], bh[3]);
                    #pragma unroll
                    for (int mt = 0; mt < 2; mt++) {
                        mma_fp16(acc[mt][ng * 2 + 0], ah[mt], bh[0], bh[1]);
                        mma_fp16(acc[mt][ng * 2 + 1], ah[mt], bh[2], bh[3]);
                    }
                }
            }
            __syncthreads();
            if (q + 2 < 4) issueB1(q + 2, q & 1);
        }

        // write z half j into swizzled smem chunks (2j, 2j+1)
        #pragma unroll
        for (int mt = 0; mt < 2; mt++) {
            #pragma unroll
            for (int rr = 0; rr < 2; rr++) {
                const int rl = m0w + mt * 16 + g + rr * 8;   // local row 0..127
                #pragma unroll
                for (int t = 0; t < 8; t++) {
                    const int colIn = n0w + t * 8 + tig * 2; // 0..126 within half
                    float b0 = __ldg(b1 + j * 128 + colIn);
                    float bb1 = __ldg(b1 + j * 128 + colIn + 1);
                    float v0 = fmaxf(acc[mt][t][rr * 2 + 0] + b0, 0.f);
                    float v1 = fmaxf(acc[mt][t][rr * 2 + 1] + bb1, 0.f);
                    __half2 hv = __float22half2_rn(make_float2(v0, v1));
                    int chunk = j * 2 + (colIn >> 6);
                    uint32_t off = (uint32_t)rl * 128 +
                                   (uint32_t)(((colIn & 63) * 2) ^ ((rl & 7) << 4));
                    *(__half2*)(smem + 32768 + chunk * 16384 + off) = hv;
                }
            }
        }
    }
    __syncthreads();   // z fully written; B stages free

    // ---- phase 2: out = z @ W2 + b2 (K=256, A = z smem) -----------------------
    #pragma unroll
    for (int a = 0; a < 2; a++)
        #pragma unroll
        for (int b = 0; b < 8; b++)
            #pragma unroll
            for (int c = 0; c < 4; c++) acc[a][b][c] = 0.f;

    issueB2(0, 0);
    issueB2(1, 1);

    #pragma unroll
    for (int c = 0; c < 4; c++) {
        if (c + 1 < 4) CP_WAIT1(); else CP_WAIT0();
        __syncthreads();
        const uint32_t As = ZB + c * 16384;
        const uint32_t Bs = BB + (c & 1) * 16384;
        #pragma unroll
        for (int kk4 = 0; kk4 < 4; kk4++) {
            const uint32_t kb = (uint32_t)kk4 * 32;
            uint32_t ah[2][4];
            #pragma unroll
            for (int mt = 0; mt < 2; mt++) {
                uint32_t ad = aoff + (uint32_t)mt * 2048 + ((kb + kxA) ^ axor);
                ldsm4(As + ad, ah[mt][0], ah[mt][1], ah[mt][2], ah[mt][3]);
            }
            #pragma unroll
            for (int ng = 0; ng < 4; ng++) {
                uint32_t bd = (uint32_t)(n0w + ng * 16 + rB) * 128 + ((kb + kxB) ^ bxor);
                uint32_t bh[4];
                ldsm4(Bs + bd, bh[0], bh[1], bh[2], bh[3]);
                #pragma unroll
                for (int mt = 0; mt < 2; mt++) {
                    mma_fp16(acc[mt][ng * 2 + 0], ah[mt], bh[0], bh[1]);
                    mma_fp16(acc[mt][ng * 2 + 1], ah[mt], bh[2], bh[3]);
                }
            }
        }
        __syncthreads();
        if (c + 2 < 4) issueB2(c + 2, c & 1);
    }

    #pragma unroll
    for (int mt = 0; mt < 2; mt++) {
        const int r0 = rowBase + m0w + mt * 16 + g;
        #pragma unroll
        for (int t = 0; t < 8; t++) {
            const int col = n0w + t * 8 + tig * 2;
            float b0 = __ldg(b2 + col), bb = __ldg(b2 + col + 1);
            if (r0 < M)
                *(float2*)&out[(size_t)r0 * FD + col] =
                    make_float2(acc[mt][t][0] + b0, acc[mt][t][1] + bb);
            if (r0 + 8 < M)
                *(float2*)&out[(size_t)(r0 + 8) * FD + col] =
                    make_float2(acc[mt][t][2] + b0, acc[mt][t][3] + bb);
        }
    }
}

// ---------------- fused gather(fp16 msgs) + LN + ReLU + residual ---------------
__global__ void __launch_bounds__(256)
gather_ln_kernel(const float* __restrict__ hself,
                 const __half* __restrict__ tmp_i, const __half* __restrict__ tmp_u,
                 const int* __restrict__ off_u, const int* __restrict__ eid_u,
                 const int* __restrict__ off_i, const int* __restrict__ eid_i,
                 const float* __restrict__ fu, const float* __restrict__ fi,
                 const float* __restrict__ gu, const float* __restrict__ bu,
                 const float* __restrict__ gi, const float* __restrict__ bi,
                 __half* __restrict__ outH,
                 int Mu, int Mt)
{
    int row = blockIdx.x * 8 + threadIdx.y;
    if (row >= Mt) return;
    int lane = threadIdx.x;
    const bool isU = row < Mu;
    const int r = isU ? row : row - Mu;
    const int* off = isU ? off_u : off_i;
    const int* eid = isU ? eid_u : eid_i;
    const __half* tmp = isU ? tmp_i : tmp_u;
    const float* feat = isU ? fu + (size_t)r * FD : fi + (size_t)r * FD;
    const float* g = isU ? gu : gi;
    const float* b = isU ? bu : bi;

    const int s0 = __ldg(&off[r]);
    const int s1 = __ldg(&off[r + 1]);

    float4 acc = *(const float4*)&hself[(size_t)row * FD + lane * 4];

    for (int base = s0; base < s1; base += 32) {
        int idx = (base + lane < s1) ? __ldg(&eid[base + lane]) : 0;
        int m = min(32, s1 - base);
        #pragma unroll 4
        for (int k = 0; k < m; k++) {
            int id = __shfl_sync(0xffffffffu, idx, k);
            uint2 raw = *(const uint2*)&tmp[(size_t)id * FD + lane * 4];
            float2 p0 = __half22float2(*(__half2*)&raw.x);
            float2 p1 = __half22float2(*(__half2*)&raw.y);
            acc.x += p0.x; acc.y += p0.y; acc.z += p1.x; acc.w += p1.y;
        }
    }

    float s = acc.x + acc.y + acc.z + acc.w;
    #pragma unroll
    for (int off2 = 16; off2 > 0; off2 >>= 1) s += __shfl_xor_sync(0xffffffffu, s, off2);
    float mean = s * (1.0f / FD);
    float dx = acc.x - mean, dy = acc.y - mean, dz = acc.z - mean, dw = acc.w - mean;
    float q = dx * dx + dy * dy + dz * dz + dw * dw;
    #pragma unroll
    for (int off2 = 16; off2 > 0; off2 >>= 1) q += __shfl_xor_sync(0xffffffffu, q, off2);
    float rstd = rsqrtf(q * (1.0f / FD) + 1e-5f);

    float4 gv = *(const float4*)&g[lane * 4];
    float4 bv = *(const float4*)&b[lane * 4];
    float4 fv = *(const float4*)&feat[lane * 4];
    float4 o;
    o.x = fmaxf(dx * rstd * gv.x + bv.x, 0.f) + fv.x;
    o.y = fmaxf(dy * rstd * gv.y + bv.y, 0.f) + fv.y;
    o.z = fmaxf(dz * rstd * gv.z + bv.z, 0.f) + fv.z;
    o.w = fmaxf(dw * rstd * gv.w + bv.w, 0.f) + fv.w;

    __half2 h01 = __float22half2_rn(make_float2(o.x, o.y));
    __half2 h23 = __float22half2_rn(make_float2(o.z, o.w));
    uint2 hv = make_uint2(*(uint32_t*)&h01, *(uint32_t*)&h23);
    *(uint2*)&outH[(size_t)row * FD + lane * 4] = hv;
}

// ---------------- launch ------------------------------------------------------
extern "C" void kernel_launch(void* const* d_in, const int* in_sizes, int n_in,
                              void* d_out, int out_size)
{
    const float* feat_user   = (const float*)d_in[0];
    const float* feat_item   = (const float*)d_in[1];
    const float* W_u2i       = (const float*)d_in[2];
    const float* b_u2i       = (const float*)d_in[3];
    const float* W_i2u       = (const float*)d_in[4];
    const float* b_i2u       = (const float*)d_in[5];
    const float* self_w_user = (const float*)d_in[6];
    const float* self_w_item = (const float*)d_in[7];
    const float* ln_g_user   = (const float*)d_in[8];
    const float* ln_b_user   = (const float*)d_in[9];
    const float* ln_g_item   = (const float*)d_in[10];
    const float* ln_b_item   = (const float*)d_in[11];
    const float* ffn_w1      = (const float*)d_in[12];
    const float* ffn_b1      = (const float*)d_in[13];
    const float* ffn_w2      = (const float*)d_in[14];
    const float* ffn_b2      = (const float*)d_in[15];
    const int*   src_u2i     = (const int*)d_in[16];
    const int*   dst_u2i     = (const int*)d_in[17];
    const int*   src_i2u     = (const int*)d_in[18];
    const int*   dst_i2u     = (const int*)d_in[19];

    const int Mu = in_sizes[0] / FD;
    const int Mi = in_sizes[1] / FD;
    const int E1 = in_sizes[16];
    const int E2 = in_sizes[18];
    float* out = (float*)d_out;

    auto sym = [](const void* s) { void* p; cudaGetSymbolAddress(&p, s); return p; };
    __half* tmp_u = (__half*)sym(g_tmp_u);
    __half* tmp_i = (__half*)sym(g_tmp_i);
    float* h      = (float*)sym(g_h);
    __half* fu = (__half*)sym(g_fu);
    __half* fi = (__half*)sym(g_fi);
    __half* hh = (__half*)sym(g_hh);
    __half* w_u2i = (__half*)sym(g_w_u2i);
    __half* w_i2u = (__half*)sym(g_w_i2u);
    __half* w_su  = (__half*)sym(g_w_su);
    __half* w_si  = (__half*)sym(g_w_si);
    __half* w_f1  = (__half*)sym(g_w_f1);
    __half* w_f2  = (__half*)sym(g_w_f2);
    int* cnt_u = (int*)sym(g_cnt_u);
    int* cnt_i = (int*)sym(g_cnt_i);
    int* off_u = (int*)sym(g_off_u);
    int* off_i = (int*)sym(g_off_i);
    int* cur_u = (int*)sym(g_cur_u);
    int* cur_i = (int*)sym(g_cur_i);
    int* eid_u = (int*)sym(g_eid_u);
    int* eid_i = (int*)sym(g_eid_i);

    float* h_user = h;
    float* h_item = h + (size_t)Mu * FD;

    cudaFuncSetAttribute(gemm_mma, cudaFuncAttributeMaxDynamicSharedMemorySize, 65536);
    cudaFuncSetAttribute(ffn_fused, cudaFuncAttributeMaxDynamicSharedMemorySize, 131072);

    static cudaStream_t s2 = nullptr;
    static cudaEvent_t evF = nullptr, evJ = nullptr;
    if (!s2) {
        cudaStreamCreateWithFlags(&s2, cudaStreamNonBlocking);
        cudaEventCreateWithFlags(&evF, cudaEventDisableTiming);
        cudaEventCreateWithFlags(&evJ, cudaEventDisableTiming);
    }

    // ---- fork: stream B builds both CSRs --------------------------------------
    cudaEventRecord(evF, 0);
    cudaStreamWaitEvent(s2, evF, 0);
    cudaMemsetAsync(cnt_u, 0, Mu * sizeof(int), s2);
    cudaMemsetAsync(cnt_i, 0, Mi * sizeof(int), s2);
    {
        int tot = E1 + E2;
        hist2_kernel<<<(tot + 255) / 256, 256, 0, s2>>>(dst_i2u, E2, cnt_u,
                                                        dst_u2i, E1, cnt_i);
        scan_kernel<<<2, 1024, 0, s2>>>(cnt_u, off_u, cur_u, Mu,
                                        cnt_i, off_i, cur_i, Mi);
        fill2_kernel<<<(tot + 255) / 256, 256, 0, s2>>>(
            src_i2u, dst_i2u, E2, cur_u, eid_u,
            src_u2i, dst_u2i, E1, cur_i, eid_i);
    }
    cudaEventRecord(evJ, s2);

    // ---- stream A: weights, feature converts, all 4 D-GEMMs in ONE launch -----
    wtrans_all<<<dim3(128, 6), 256>>>(W_u2i, W_i2u, self_w_user, self_w_item,
                                      ffn_w1, ffn_w2,
                                      w_u2i, w_i2u, w_su, w_si, w_f1, w_f2);
    const int n4u = Mu * FD / 4, n4i = Mi * FD / 4;
    const int gx2 = (max(n4u, n4i) + 255) / 256;
    conv2_kernel<<<dim3(gx2, 2), 256>>>(feat_user, fu, n4u, feat_item, fi, n4i);
    {
        GemmArgs a{};
        a.K = FD; a.ldC = FD; a.relu = 0;
        a.s[0] = { fu, w_u2i, nullptr, nullptr, tmp_u, Mu, 0 };
        a.s[1] = { fu, w_su,  b_i2u,   h_user,  nullptr, Mu, 0 };
        a.s[2] = { fi, w_i2u, nullptr, nullptr, tmp_i, Mi, 0 };
        a.s[3] = { fi, w_si,  b_u2i,   h_item,  nullptr, Mi, 0 };
        int gx = (max(Mu, Mi) + 127) / 128;
        gemm_mma<<<dim3(gx, 4), 256, 65536>>>(a);
    }

    // ---- join: fused gather(fp16) + LN + ReLU + residual ----------------------
    cudaStreamWaitEvent(0, evJ, 0);
    const int Mt = Mu + Mi;
    {
        dim3 lblk(32, 8);
        gather_ln_kernel<<<(Mt + 7) / 8, lblk>>>(
            h, tmp_i, tmp_u, off_u, eid_u, off_i, eid_i,
            feat_user, feat_item,
            ln_g_user, ln_b_user, ln_g_item, ln_b_item,
            hh, Mu, Mt);
    }

    // ---- fused FFN ------------------------------------------------------------
    ffn_fused<<<(Mt + 127) / 128, 256, 131072>>>(hh, w_f1, ffn_b1, w_f2, ffn_b2,
                                                 out, Mt);
}